// round 2
// baseline (speedup 1.0000x reference)
#include <cuda_runtime.h>

#define BB 4
#define NN 256
#define DD 256
#define M_PER_B (NN*NN)   // 65536
#define TILE_M 64
#define KSPLIT 64
#define KCHUNK (M_PER_B/KSPLIT)  // 1024
#define NBLK 4            // pass B n-slices of 64

// ---- device scratch (static globals: allocation-free) ----
__device__ float g_A[BB*NN*DD];                    // A[b][n][h], includes 1/sqrt(D)
__device__ float g_c[BB*NN];                       // bq . k_n / sqrt(D)
__device__ float g_P[(size_t)BB*M_PER_B*NN];       // probs [b][m][n]  (256 MiB)
__device__ float g_W[(size_t)BB*KSPLIT*NBLK*64*256]; // split-K partials of G (64 MiB)
__device__ float g_Wt[BB*KSPLIT*NBLK*64];          // split-K partials of t[n]

// =====================================================================
// Kernel 1: K = hidden@Wk + bk ; A[b][n][h] = (Wq[h,:].K[b,n,:])/16 ;
//           c[b][n] = (bq . K[b,n,:])/16
// grid (256 n, 4 b), 256 threads
// =====================================================================
__global__ void __launch_bounds__(256) prep_kernel(
    const float* __restrict__ hidden,
    const float* __restrict__ Wq, const float* __restrict__ bq,
    const float* __restrict__ Wk, const float* __restrict__ bk)
{
    int n = blockIdx.x, b = blockIdx.y, t = threadIdx.x;
    __shared__ float hrow[256];
    __shared__ float krow[256];
    hrow[t] = hidden[(b*256 + n)*256 + t];
    __syncthreads();

    // k_d = sum_h hrow[h] * Wk[h][d] + bk[d]   (coalesced over d=t)
    float a = bk[t];
    #pragma unroll 8
    for (int h = 0; h < 256; h++) a += hrow[h] * Wk[h*256 + t];
    krow[t] = a;
    __syncthreads();

    int lane = t & 31, w = t >> 5;
    const float sc = 0.0625f;  // 1/sqrt(256)
    // A[n][h]: warp-per-h, lanes over d, shuffle reduce
    for (int h = w; h < 256; h += 8) {
        float s = 0.f;
        #pragma unroll 4
        for (int d = lane; d < 256; d += 32) s += Wq[h*256 + d] * krow[d];
        #pragma unroll
        for (int of = 16; of > 0; of >>= 1) s += __shfl_xor_sync(0xffffffffu, s, of);
        if (lane == 0) g_A[(b*256 + n)*256 + h] = s * sc;
    }
    if (w == 0) {
        float s = 0.f;
        #pragma unroll 4
        for (int d = lane; d < 256; d += 32) s += bq[d] * krow[d];
        #pragma unroll
        for (int of = 16; of > 0; of >>= 1) s += __shfl_xor_sync(0xffffffffu, s, of);
        if (lane == 0) g_c[b*256 + n] = s * sc;
    }
}

// =====================================================================
// Kernel 2 (pass A): scores_tile = S_tile @ A_b ; +c[n]+mask2d[m] ; relu ;
//                    row-normalize ; write P
// grid (1024 m-tiles, 4 b), 256 threads, TILE_M=64
// thread layout: warp w -> m rows [w*8, w*8+8), lane -> n cols lane*8..+8
// smem: Ssm transposed [k=256][m=64] stride 65 ; Asm transposed [kk=32][n=256] stride 260
// =====================================================================
__global__ void __launch_bounds__(256, 2) passA_kernel(
    const float* __restrict__ S, const float* __restrict__ am)
{
    extern __shared__ float sh[];
    float* Ssm = sh;              // 256*65 = 16640 floats
    float* Asm = sh + 256*65;     // 32*260 = 8320 floats

    int b = blockIdx.y;
    int m0 = blockIdx.x * TILE_M;
    int tid = threadIdx.x, lane = tid & 31, w = tid >> 5;
    const float* Sb = S + ((size_t)b*M_PER_B + m0)*256;

    // load S tile, transpose into Ssm[k][m] (stride 65 -> conflict-free writes)
    #pragma unroll
    for (int idx = tid; idx < 64*64; idx += 256) {
        int m = idx >> 6, k4 = (idx & 63) << 2;
        float4 v = *reinterpret_cast<const float4*>(Sb + (size_t)m*256 + k4);
        Ssm[(k4+0)*65 + m] = v.x;
        Ssm[(k4+1)*65 + m] = v.y;
        Ssm[(k4+2)*65 + m] = v.z;
        Ssm[(k4+3)*65 + m] = v.w;
    }

    float acc[8][8];
    #pragma unroll
    for (int i = 0; i < 8; i++)
        #pragma unroll
        for (int j = 0; j < 8; j++) acc[i][j] = 0.f;

    const float* Ab = g_A + (size_t)b*NN*DD;  // [n][h]

    for (int k0 = 0; k0 < 256; k0 += 32) {
        __syncthreads();
        // load A chunk transposed: Asm[kk][n]
        #pragma unroll
        for (int idx = tid; idx < 256*32; idx += 256) {
            int n = idx >> 5, kk = idx & 31;
            Asm[kk*260 + n] = Ab[n*256 + k0 + kk];
        }
        __syncthreads();
        #pragma unroll 8
        for (int kk = 0; kk < 32; kk++) {
            float sreg[8];
            const float* Sk = Ssm + (k0 + kk)*65 + w*8;
            #pragma unroll
            for (int i = 0; i < 8; i++) sreg[i] = Sk[i];     // broadcast
            float4 a0 = *reinterpret_cast<const float4*>(Asm + kk*260 + lane*8);
            float4 a1 = *reinterpret_cast<const float4*>(Asm + kk*260 + lane*8 + 4);
            float areg[8] = {a0.x, a0.y, a0.z, a0.w, a1.x, a1.y, a1.z, a1.w};
            #pragma unroll
            for (int i = 0; i < 8; i++)
                #pragma unroll
                for (int j = 0; j < 8; j++)
                    acc[i][j] += sreg[i] * areg[j];
        }
    }

    // epilogue: + c[n] + mask2d[m], relu, normalize over n, store P
    float cv[8];
    #pragma unroll
    for (int j = 0; j < 8; j++) cv[j] = g_c[b*NN + lane*8 + j];
    const float* amb = am + b*NN;
    #pragma unroll
    for (int i = 0; i < 8; i++) {
        int mg = m0 + w*8 + i;
        float mv = amb[mg >> 8] * amb[mg & 255];
        float rs = 0.f;
        #pragma unroll
        for (int j = 0; j < 8; j++) {
            float v = fmaxf(acc[i][j] + cv[j] + mv, 0.f);
            acc[i][j] = v;
            rs += v;
        }
        #pragma unroll
        for (int of = 16; of > 0; of >>= 1) rs += __shfl_xor_sync(0xffffffffu, rs, of);
        float inv = 1.f / (rs + 2.56e-10f);   // sum(p + 1e-12) over 256
        float4 o0, o1;
        o0.x = acc[i][0]*inv; o0.y = acc[i][1]*inv; o0.z = acc[i][2]*inv; o0.w = acc[i][3]*inv;
        o1.x = acc[i][4]*inv; o1.y = acc[i][5]*inv; o1.z = acc[i][6]*inv; o1.w = acc[i][7]*inv;
        size_t po = ((size_t)b*M_PER_B + mg)*256 + lane*8;
        *reinterpret_cast<float4*>(g_P + po)     = o0;
        *reinterpret_cast<float4*>(g_P + po + 4) = o1;
    }
}

// =====================================================================
// Kernel 3 (pass B): G_partial[nslice, h] = sum_{m in chunk} P[m,n] S[m,h]
//                    and t_partial[n] = sum_m P[m,n]
// grid (64 ksplit, 4 nblk, 4 b), 256 threads
// warp w -> n-local rows w*8..+8 (of 64-wide slice), lane -> h cols lane*8..+8
// =====================================================================
__global__ void __launch_bounds__(256, 2) passB_kernel(const float* __restrict__ S)
{
    __shared__ __align__(16) float Psm[32*64];
    __shared__ __align__(16) float Vsm[32*256];

    int ks = blockIdx.x, nb = blockIdx.y, b = blockIdx.z;
    int tid = threadIdx.x, lane = tid & 31, w = tid >> 5;

    float acc[8][8];
    #pragma unroll
    for (int i = 0; i < 8; i++)
        #pragma unroll
        for (int j = 0; j < 8; j++) acc[i][j] = 0.f;
    float tpart = 0.f;

    const float* Sb = S   + (size_t)b*M_PER_B*256;
    const float* Pb = g_P + (size_t)b*M_PER_B*256;
    int mbase0 = ks * KCHUNK;

    for (int it = 0; it < KCHUNK/32; it++) {
        int mb = mbase0 + it*32;
        __syncthreads();
        // load P tile [32 m][64 n-slice]
        #pragma unroll
        for (int idx = tid; idx < 512; idx += 256) {
            int r = idx >> 4, n4 = (idx & 15) << 2;
            *reinterpret_cast<float4*>(&Psm[r*64 + n4]) =
                *reinterpret_cast<const float4*>(&Pb[(size_t)(mb + r)*256 + nb*64 + n4]);
        }
        // load S tile [32 m][256 h]
        #pragma unroll
        for (int idx = tid; idx < 2048; idx += 256) {
            int r = idx >> 6, h4 = (idx & 63) << 2;
            *reinterpret_cast<float4*>(&Vsm[r*256 + h4]) =
                *reinterpret_cast<const float4*>(&Sb[(size_t)(mb + r)*256 + h4]);
        }
        __syncthreads();
        if (tid < 64) {
            #pragma unroll 8
            for (int mm = 0; mm < 32; mm++) tpart += Psm[mm*64 + tid];
        }
        #pragma unroll 8
        for (int mm = 0; mm < 32; mm++) {
            float p[8];
            #pragma unroll
            for (int i = 0; i < 8; i++) p[i] = Psm[mm*64 + w*8 + i];  // broadcast
            float4 s0 = *reinterpret_cast<const float4*>(&Vsm[mm*256 + lane*8]);
            float4 s1 = *reinterpret_cast<const float4*>(&Vsm[mm*256 + lane*8 + 4]);
            float sv[8] = {s0.x, s0.y, s0.z, s0.w, s1.x, s1.y, s1.z, s1.w};
            #pragma unroll
            for (int i = 0; i < 8; i++)
                #pragma unroll
                for (int j = 0; j < 8; j++)
                    acc[i][j] += p[i] * sv[j];
        }
    }

    size_t base = (((size_t)b*KSPLIT + ks)*NBLK + nb)*64;
    #pragma unroll
    for (int i = 0; i < 8; i++) {
        size_t o = (base + w*8 + i)*256 + lane*8;
        float4 o0, o1;
        o0.x = acc[i][0]; o0.y = acc[i][1]; o0.z = acc[i][2]; o0.w = acc[i][3];
        o1.x = acc[i][4]; o1.y = acc[i][5]; o1.z = acc[i][6]; o1.w = acc[i][7];
        *reinterpret_cast<float4*>(g_W + o)     = o0;
        *reinterpret_cast<float4*>(g_W + o + 4) = o1;
    }
    if (tid < 64) g_Wt[base + tid] = tpart;
}

// =====================================================================
// Kernel 4: reduce split-K -> G row, t ; context = G@Wv + t*bv ;
//           out = context@Wo + bo ; y = LN(out + hidden)
// grid (256 n, 4 b), 256 threads
// =====================================================================
__global__ void __launch_bounds__(256) final_kernel(
    const float* __restrict__ hidden,
    const float* __restrict__ Wv, const float* __restrict__ bv,
    const float* __restrict__ Wo, const float* __restrict__ bo,
    const float* __restrict__ gamma, const float* __restrict__ beta,
    float* __restrict__ out)
{
    int n = blockIdx.x, b = blockIdx.y, t = threadIdx.x;
    __shared__ float grow[256];
    __shared__ float crow[256];
    __shared__ float red[64];
    __shared__ float wsum[8];

    int nb = n >> 6, nl = n & 63;
    float g = 0.f;
    #pragma unroll 8
    for (int ks = 0; ks < KSPLIT; ks++)
        g += g_W[((((size_t)b*KSPLIT + ks)*NBLK + nb)*64 + nl)*256 + t];
    grow[t] = g;
    if (t < 64)
        red[t] = g_Wt[(((size_t)b*KSPLIT + t)*NBLK + nb)*64 + nl];
    __syncthreads();

    float tsum = 0.f;
    #pragma unroll
    for (int i = 0; i < 64; i++) tsum += red[i];

    // context_d = sum_h G[n,h] Wv[h][d] + tsum*bv[d]
    float c = tsum * bv[t];
    #pragma unroll 8
    for (int h = 0; h < 256; h++) c += grow[h] * Wv[h*256 + t];
    crow[t] = c;
    __syncthreads();

    // out_h = sum_d c[d] Wo[d][h] + bo[h]
    float o = bo[t];
    #pragma unroll 8
    for (int d = 0; d < 256; d++) o += crow[d] * Wo[d*256 + t];
    float x = o + hidden[(b*256 + n)*256 + t];

    // LayerNorm over 256 (block-wide)
    int lane = t & 31, w = t >> 5;
    float s = x;
    #pragma unroll
    for (int of = 16; of > 0; of >>= 1) s += __shfl_xor_sync(0xffffffffu, s, of);
    if (lane == 0) wsum[w] = s;
    __syncthreads();
    float tot = 0.f;
    #pragma unroll
    for (int i = 0; i < 8; i++) tot += wsum[i];
    float mean = tot * (1.f/256.f);
    float dx = x - mean;
    __syncthreads();

    float s2 = dx * dx;
    #pragma unroll
    for (int of = 16; of > 0; of >>= 1) s2 += __shfl_xor_sync(0xffffffffu, s2, of);
    if (lane == 0) wsum[w] = s2;
    __syncthreads();
    float tot2 = 0.f;
    #pragma unroll
    for (int i = 0; i < 8; i++) tot2 += wsum[i];
    float var = tot2 * (1.f/256.f);

    out[(b*256 + n)*256 + t] = gamma[t] * dx * rsqrtf(var + 1e-5f) + beta[t];
}

// =====================================================================
extern "C" void kernel_launch(void* const* d_in, const int* in_sizes, int n_in,
                              void* d_out, int out_size)
{
    const float* hidden = (const float*)d_in[0];
    const float* S      = (const float*)d_in[1];
    const float* am     = (const float*)d_in[2];
    const float* Wq     = (const float*)d_in[3];
    const float* bq     = (const float*)d_in[4];
    const float* Wk     = (const float*)d_in[5];
    const float* bk     = (const float*)d_in[6];
    const float* Wv     = (const float*)d_in[7];
    const float* bv     = (const float*)d_in[8];
    const float* Wo     = (const float*)d_in[9];
    const float* bo     = (const float*)d_in[10];
    const float* gamma  = (const float*)d_in[11];
    const float* beta   = (const float*)d_in[12];
    float* out          = (float*)d_out;

    const int smemA = (256*65 + 32*260) * sizeof(float);  // 99840 B
    cudaFuncSetAttribute(passA_kernel, cudaFuncAttributeMaxDynamicSharedMemorySize, smemA);

    prep_kernel<<<dim3(256, 4), 256>>>(hidden, Wq, bq, Wk, bk);
    passA_kernel<<<dim3(M_PER_B/TILE_M, 4), 256, smemA>>>(S, am);
    passB_kernel<<<dim3(KSPLIT, NBLK, 4), 256>>>(S);
    final_kernel<<<dim3(256, 4), 256>>>(hidden, Wv, bv, Wo, bo, gamma, beta, out);
}

// round 3
// speedup vs baseline: 1.0002x; 1.0002x over previous
#include <cuda_runtime.h>

#define BB 4
#define NN 256
#define DD 256
#define M_PER_B (NN*NN)   // 65536
#define TILE_M 64
#define KSPLIT 64
#define KCHUNK (M_PER_B/KSPLIT)  // 1024
#define NBLK 4            // pass B n-slices of 64

// ---- device scratch (static globals: allocation-free) ----
__device__ float g_A[BB*NN*DD];                    // A[b][n][h], includes 1/sqrt(D)
__device__ float g_c[BB*NN];                       // bq . k_n / sqrt(D)
__device__ float g_P[(size_t)BB*M_PER_B*NN];       // probs [b][m][n]  (256 MiB)
__device__ float g_W[(size_t)BB*KSPLIT*NBLK*64*256]; // split-K partials of G (64 MiB)
__device__ float g_Wt[BB*KSPLIT*NBLK*64];          // split-K partials of t[n]

// =====================================================================
// Kernel 1: K = hidden@Wk + bk ; A[b][n][h] = (Wq[h,:].K[b,n,:])/16 ;
//           c[b][n] = (bq . K[b,n,:])/16
// grid (256 n, 4 b), 256 threads
// =====================================================================
__global__ void __launch_bounds__(256) prep_kernel(
    const float* __restrict__ hidden,
    const float* __restrict__ Wq, const float* __restrict__ bq,
    const float* __restrict__ Wk, const float* __restrict__ bk)
{
    int n = blockIdx.x, b = blockIdx.y, t = threadIdx.x;
    __shared__ float hrow[256];
    __shared__ float krow[256];
    hrow[t] = hidden[(b*256 + n)*256 + t];
    __syncthreads();

    // k_d = sum_h hrow[h] * Wk[h][d] + bk[d]   (coalesced over d=t)
    float a = bk[t];
    #pragma unroll 8
    for (int h = 0; h < 256; h++) a += hrow[h] * Wk[h*256 + t];
    krow[t] = a;
    __syncthreads();

    int lane = t & 31, w = t >> 5;
    const float sc = 0.0625f;  // 1/sqrt(256)
    // A[n][h]: warp-per-h, lanes over d, shuffle reduce
    for (int h = w; h < 256; h += 8) {
        float s = 0.f;
        #pragma unroll 4
        for (int d = lane; d < 256; d += 32) s += Wq[h*256 + d] * krow[d];
        #pragma unroll
        for (int of = 16; of > 0; of >>= 1) s += __shfl_xor_sync(0xffffffffu, s, of);
        if (lane == 0) g_A[(b*256 + n)*256 + h] = s * sc;
    }
    if (w == 0) {
        float s = 0.f;
        #pragma unroll 4
        for (int d = lane; d < 256; d += 32) s += bq[d] * krow[d];
        #pragma unroll
        for (int of = 16; of > 0; of >>= 1) s += __shfl_xor_sync(0xffffffffu, s, of);
        if (lane == 0) g_c[b*256 + n] = s * sc;
    }
}

// =====================================================================
// Kernel 2 (pass A): scores_tile = S_tile @ A_b ; +c[n]+mask2d[m] ; relu ;
//                    row-normalize ; write P
// grid (1024 m-tiles, 4 b), 256 threads, TILE_M=64
// thread layout: warp w -> m rows [w*8, w*8+8), lane -> n cols lane*8..+8
// smem: Ssm transposed [k=256][m=64] stride 65 ; Asm transposed [kk=32][n=256] stride 260
// =====================================================================
__global__ void __launch_bounds__(256, 2) passA_kernel(
    const float* __restrict__ S, const float* __restrict__ am)
{
    extern __shared__ float sh[];
    float* Ssm = sh;              // 256*65 = 16640 floats
    float* Asm = sh + 256*65;     // 32*260 = 8320 floats

    int b = blockIdx.y;
    int m0 = blockIdx.x * TILE_M;
    int tid = threadIdx.x, lane = tid & 31, w = tid >> 5;
    const float* Sb = S + ((size_t)b*M_PER_B + m0)*256;

    // load S tile, transpose into Ssm[k][m] (stride 65 -> conflict-free writes)
    #pragma unroll
    for (int idx = tid; idx < 64*64; idx += 256) {
        int m = idx >> 6, k4 = (idx & 63) << 2;
        float4 v = *reinterpret_cast<const float4*>(Sb + (size_t)m*256 + k4);
        Ssm[(k4+0)*65 + m] = v.x;
        Ssm[(k4+1)*65 + m] = v.y;
        Ssm[(k4+2)*65 + m] = v.z;
        Ssm[(k4+3)*65 + m] = v.w;
    }

    float acc[8][8];
    #pragma unroll
    for (int i = 0; i < 8; i++)
        #pragma unroll
        for (int j = 0; j < 8; j++) acc[i][j] = 0.f;

    const float* Ab = g_A + (size_t)b*NN*DD;  // [n][h]

    for (int k0 = 0; k0 < 256; k0 += 32) {
        __syncthreads();
        // load A chunk transposed: Asm[kk][n]
        #pragma unroll
        for (int idx = tid; idx < 256*32; idx += 256) {
            int n = idx >> 5, kk = idx & 31;
            Asm[kk*260 + n] = Ab[n*256 + k0 + kk];
        }
        __syncthreads();
        #pragma unroll 8
        for (int kk = 0; kk < 32; kk++) {
            float sreg[8];
            const float* Sk = Ssm + (k0 + kk)*65 + w*8;
            #pragma unroll
            for (int i = 0; i < 8; i++) sreg[i] = Sk[i];     // broadcast
            float4 a0 = *reinterpret_cast<const float4*>(Asm + kk*260 + lane*8);
            float4 a1 = *reinterpret_cast<const float4*>(Asm + kk*260 + lane*8 + 4);
            float areg[8] = {a0.x, a0.y, a0.z, a0.w, a1.x, a1.y, a1.z, a1.w};
            #pragma unroll
            for (int i = 0; i < 8; i++)
                #pragma unroll
                for (int j = 0; j < 8; j++)
                    acc[i][j] += sreg[i] * areg[j];
        }
    }

    // epilogue: + c[n] + mask2d[m], relu, normalize over n, store P
    float cv[8];
    #pragma unroll
    for (int j = 0; j < 8; j++) cv[j] = g_c[b*NN + lane*8 + j];
    const float* amb = am + b*NN;
    #pragma unroll
    for (int i = 0; i < 8; i++) {
        int mg = m0 + w*8 + i;
        float mv = amb[mg >> 8] * amb[mg & 255];
        float rs = 0.f;
        #pragma unroll
        for (int j = 0; j < 8; j++) {
            float v = fmaxf(acc[i][j] + cv[j] + mv, 0.f);
            acc[i][j] = v;
            rs += v;
        }
        #pragma unroll
        for (int of = 16; of > 0; of >>= 1) rs += __shfl_xor_sync(0xffffffffu, rs, of);
        float inv = 1.f / (rs + 2.56e-10f);   // sum(p + 1e-12) over 256
        float4 o0, o1;
        o0.x = acc[i][0]*inv; o0.y = acc[i][1]*inv; o0.z = acc[i][2]*inv; o0.w = acc[i][3]*inv;
        o1.x = acc[i][4]*inv; o1.y = acc[i][5]*inv; o1.z = acc[i][6]*inv; o1.w = acc[i][7]*inv;
        size_t po = ((size_t)b*M_PER_B + mg)*256 + lane*8;
        *reinterpret_cast<float4*>(g_P + po)     = o0;
        *reinterpret_cast<float4*>(g_P + po + 4) = o1;
    }
}

// =====================================================================
// Kernel 3 (pass B): G_partial[nslice, h] = sum_{m in chunk} P[m,n] S[m,h]
//                    and t_partial[n] = sum_m P[m,n]
// grid (64 ksplit, 4 nblk, 4 b), 256 threads
// warp w -> n-local rows w*8..+8 (of 64-wide slice), lane -> h cols lane*8..+8
// =====================================================================
__global__ void __launch_bounds__(256, 2) passB_kernel(const float* __restrict__ S)
{
    __shared__ __align__(16) float Psm[32*64];
    __shared__ __align__(16) float Vsm[32*256];

    int ks = blockIdx.x, nb = blockIdx.y, b = blockIdx.z;
    int tid = threadIdx.x, lane = tid & 31, w = tid >> 5;

    float acc[8][8];
    #pragma unroll
    for (int i = 0; i < 8; i++)
        #pragma unroll
        for (int j = 0; j < 8; j++) acc[i][j] = 0.f;
    float tpart = 0.f;

    const float* Sb = S   + (size_t)b*M_PER_B*256;
    const float* Pb = g_P + (size_t)b*M_PER_B*256;
    int mbase0 = ks * KCHUNK;

    for (int it = 0; it < KCHUNK/32; it++) {
        int mb = mbase0 + it*32;
        __syncthreads();
        // load P tile [32 m][64 n-slice]
        #pragma unroll
        for (int idx = tid; idx < 512; idx += 256) {
            int r = idx >> 4, n4 = (idx & 15) << 2;
            *reinterpret_cast<float4*>(&Psm[r*64 + n4]) =
                *reinterpret_cast<const float4*>(&Pb[(size_t)(mb + r)*256 + nb*64 + n4]);
        }
        // load S tile [32 m][256 h]
        #pragma unroll
        for (int idx = tid; idx < 2048; idx += 256) {
            int r = idx >> 6, h4 = (idx & 63) << 2;
            *reinterpret_cast<float4*>(&Vsm[r*256 + h4]) =
                *reinterpret_cast<const float4*>(&Sb[(size_t)(mb + r)*256 + h4]);
        }
        __syncthreads();
        if (tid < 64) {
            #pragma unroll 8
            for (int mm = 0; mm < 32; mm++) tpart += Psm[mm*64 + tid];
        }
        #pragma unroll 8
        for (int mm = 0; mm < 32; mm++) {
            float p[8];
            #pragma unroll
            for (int i = 0; i < 8; i++) p[i] = Psm[mm*64 + w*8 + i];  // broadcast
            float4 s0 = *reinterpret_cast<const float4*>(&Vsm[mm*256 + lane*8]);
            float4 s1 = *reinterpret_cast<const float4*>(&Vsm[mm*256 + lane*8 + 4]);
            float sv[8] = {s0.x, s0.y, s0.z, s0.w, s1.x, s1.y, s1.z, s1.w};
            #pragma unroll
            for (int i = 0; i < 8; i++)
                #pragma unroll
                for (int j = 0; j < 8; j++)
                    acc[i][j] += p[i] * sv[j];
        }
    }

    size_t base = (((size_t)b*KSPLIT + ks)*NBLK + nb)*64;
    #pragma unroll
    for (int i = 0; i < 8; i++) {
        size_t o = (base + w*8 + i)*256 + lane*8;
        float4 o0, o1;
        o0.x = acc[i][0]; o0.y = acc[i][1]; o0.z = acc[i][2]; o0.w = acc[i][3];
        o1.x = acc[i][4]; o1.y = acc[i][5]; o1.z = acc[i][6]; o1.w = acc[i][7];
        *reinterpret_cast<float4*>(g_W + o)     = o0;
        *reinterpret_cast<float4*>(g_W + o + 4) = o1;
    }
    if (tid < 64) g_Wt[base + tid] = tpart;
}

// =====================================================================
// Kernel 4: reduce split-K -> G row, t ; context = G@Wv + t*bv ;
//           out = context@Wo + bo ; y = LN(out + hidden)
// grid (256 n, 4 b), 256 threads
// =====================================================================
__global__ void __launch_bounds__(256) final_kernel(
    const float* __restrict__ hidden,
    const float* __restrict__ Wv, const float* __restrict__ bv,
    const float* __restrict__ Wo, const float* __restrict__ bo,
    const float* __restrict__ gamma, const float* __restrict__ beta,
    float* __restrict__ out)
{
    int n = blockIdx.x, b = blockIdx.y, t = threadIdx.x;
    __shared__ float grow[256];
    __shared__ float crow[256];
    __shared__ float red[64];
    __shared__ float wsum[8];

    int nb = n >> 6, nl = n & 63;
    float g = 0.f;
    #pragma unroll 8
    for (int ks = 0; ks < KSPLIT; ks++)
        g += g_W[((((size_t)b*KSPLIT + ks)*NBLK + nb)*64 + nl)*256 + t];
    grow[t] = g;
    if (t < 64)
        red[t] = g_Wt[(((size_t)b*KSPLIT + t)*NBLK + nb)*64 + nl];
    __syncthreads();

    float tsum = 0.f;
    #pragma unroll
    for (int i = 0; i < 64; i++) tsum += red[i];

    // context_d = sum_h G[n,h] Wv[h][d] + tsum*bv[d]
    float c = tsum * bv[t];
    #pragma unroll 8
    for (int h = 0; h < 256; h++) c += grow[h] * Wv[h*256 + t];
    crow[t] = c;
    __syncthreads();

    // out_h = sum_d c[d] Wo[d][h] + bo[h]
    float o = bo[t];
    #pragma unroll 8
    for (int d = 0; d < 256; d++) o += crow[d] * Wo[d*256 + t];
    float x = o + hidden[(b*256 + n)*256 + t];

    // LayerNorm over 256 (block-wide)
    int lane = t & 31, w = t >> 5;
    float s = x;
    #pragma unroll
    for (int of = 16; of > 0; of >>= 1) s += __shfl_xor_sync(0xffffffffu, s, of);
    if (lane == 0) wsum[w] = s;
    __syncthreads();
    float tot = 0.f;
    #pragma unroll
    for (int i = 0; i < 8; i++) tot += wsum[i];
    float mean = tot * (1.f/256.f);
    float dx = x - mean;
    __syncthreads();

    float s2 = dx * dx;
    #pragma unroll
    for (int of = 16; of > 0; of >>= 1) s2 += __shfl_xor_sync(0xffffffffu, s2, of);
    if (lane == 0) wsum[w] = s2;
    __syncthreads();
    float tot2 = 0.f;
    #pragma unroll
    for (int i = 0; i < 8; i++) tot2 += wsum[i];
    float var = tot2 * (1.f/256.f);

    out[(b*256 + n)*256 + t] = gamma[t] * dx * rsqrtf(var + 1e-5f) + beta[t];
}

// =====================================================================
extern "C" void kernel_launch(void* const* d_in, const int* in_sizes, int n_in,
                              void* d_out, int out_size)
{
    const float* hidden = (const float*)d_in[0];
    const float* S      = (const float*)d_in[1];
    const float* am     = (const float*)d_in[2];
    const float* Wq     = (const float*)d_in[3];
    const float* bq     = (const float*)d_in[4];
    const float* Wk     = (const float*)d_in[5];
    const float* bk     = (const float*)d_in[6];
    const float* Wv     = (const float*)d_in[7];
    const float* bv     = (const float*)d_in[8];
    const float* Wo     = (const float*)d_in[9];
    const float* bo     = (const float*)d_in[10];
    const float* gamma  = (const float*)d_in[11];
    const float* beta   = (const float*)d_in[12];
    float* out          = (float*)d_out;

    const int smemA = (256*65 + 32*260) * sizeof(float);  // 99840 B
    cudaFuncSetAttribute(passA_kernel, cudaFuncAttributeMaxDynamicSharedMemorySize, smemA);

    prep_kernel<<<dim3(256, 4), 256>>>(hidden, Wq, bq, Wk, bk);
    passA_kernel<<<dim3(M_PER_B/TILE_M, 4), 256, smemA>>>(S, am);
    passB_kernel<<<dim3(KSPLIT, NBLK, 4), 256>>>(S);
    final_kernel<<<dim3(256, 4), 256>>>(hidden, Wv, bv, Wo, bo, gamma, beta, out);
}

// round 4
// speedup vs baseline: 1.0269x; 1.0267x over previous
#include <cuda_runtime.h>

#define BB 4
#define NN 256
#define DD 256
#define M_PER_B (NN*NN)   // 65536
#define TILE_M 64
#define KSPLIT 64
#define KCHUNK (M_PER_B/KSPLIT)  // 1024
#define NBLK 4            // pass B n-slices of 64

// ---- device scratch (static globals: allocation-free) ----
__device__ float g_A[BB*NN*DD];                    // A[b][n][h], includes 1/sqrt(D)
__device__ float g_c[BB*NN];                       // bq . k_n / sqrt(D)
__device__ float g_P[(size_t)BB*M_PER_B*NN];       // probs [b][m][n]  (256 MiB)
__device__ float g_W[(size_t)BB*KSPLIT*NBLK*64*256]; // split-K partials of G (64 MiB)
__device__ float g_Wt[BB*KSPLIT*NBLK*64];          // split-K partials of t[n]

// ---- packed f32x2 helpers (FFMA2: 2 fp32 FMAs per issue slot) ----
__device__ __forceinline__ unsigned long long pack2(float x) {
    unsigned long long r;
    unsigned int b = __float_as_uint(x);
    asm("mov.b64 %0, {%1, %1};" : "=l"(r) : "r"(b));
    return r;
}
__device__ __forceinline__ void fma2(unsigned long long& d,
                                     unsigned long long a,
                                     unsigned long long b) {
    asm("fma.rn.f32x2 %0, %1, %2, %0;" : "+l"(d) : "l"(a), "l"(b));
}
__device__ __forceinline__ float2 unpack2(unsigned long long v) {
    unsigned int lo, hi;
    asm("mov.b64 {%0, %1}, %2;" : "=r"(lo), "=r"(hi) : "l"(v));
    return make_float2(__uint_as_float(lo), __uint_as_float(hi));
}

// =====================================================================
// Kernel 1: K = hidden@Wk + bk ; A[b][n][h] = (Wq[h,:].K[b,n,:])/16 ;
//           c[b][n] = (bq . K[b,n,:])/16
// grid (256 n, 4 b), 256 threads
// =====================================================================
__global__ void __launch_bounds__(256) prep_kernel(
    const float* __restrict__ hidden,
    const float* __restrict__ Wq, const float* __restrict__ bq,
    const float* __restrict__ Wk, const float* __restrict__ bk)
{
    int n = blockIdx.x, b = blockIdx.y, t = threadIdx.x;
    __shared__ float hrow[256];
    __shared__ float krow[256];
    hrow[t] = hidden[(b*256 + n)*256 + t];
    __syncthreads();

    // k_d = sum_h hrow[h] * Wk[h][d] + bk[d]   (coalesced over d=t)
    float a = bk[t];
    #pragma unroll 8
    for (int h = 0; h < 256; h++) a += hrow[h] * Wk[h*256 + t];
    krow[t] = a;
    __syncthreads();

    int lane = t & 31, w = t >> 5;
    const float sc = 0.0625f;  // 1/sqrt(256)
    // A[n][h]: warp-per-h, lanes over d, shuffle reduce
    for (int h = w; h < 256; h += 8) {
        float s = 0.f;
        #pragma unroll 4
        for (int d = lane; d < 256; d += 32) s += Wq[h*256 + d] * krow[d];
        #pragma unroll
        for (int of = 16; of > 0; of >>= 1) s += __shfl_xor_sync(0xffffffffu, s, of);
        if (lane == 0) g_A[(b*256 + n)*256 + h] = s * sc;
    }
    if (w == 0) {
        float s = 0.f;
        #pragma unroll 4
        for (int d = lane; d < 256; d += 32) s += bq[d] * krow[d];
        #pragma unroll
        for (int of = 16; of > 0; of >>= 1) s += __shfl_xor_sync(0xffffffffu, s, of);
        if (lane == 0) g_c[b*256 + n] = s * sc;
    }
}

// =====================================================================
// Kernel 2 (pass A): scores_tile = S_tile @ A_b ; +c[n]+mask2d[m] ; relu ;
//                    row-normalize ; write P.   FFMA2 microkernel.
// grid (1024 m-tiles, 4 b), 256 threads, TILE_M=64
// warp w -> m rows [w*8, w*8+8), lane -> n cols lane*8..+8 (4 f32x2 pairs)
// =====================================================================
__global__ void __launch_bounds__(256, 2) passA_kernel(
    const float* __restrict__ S, const float* __restrict__ am)
{
    extern __shared__ float sh[];
    float* Ssm = sh;              // 256*65 = 16640 floats  (S transposed [k][m])
    float* Asm = sh + 256*65;     // 32*260 = 8320 floats   (A chunk transposed [kk][n])

    int b = blockIdx.y;
    int m0 = blockIdx.x * TILE_M;
    int tid = threadIdx.x, lane = tid & 31, w = tid >> 5;
    const float* Sb = S + ((size_t)b*M_PER_B + m0)*256;

    // load S tile, transpose into Ssm[k][m] (stride 65 -> conflict-free writes)
    #pragma unroll
    for (int idx = tid; idx < 64*64; idx += 256) {
        int m = idx >> 6, k4 = (idx & 63) << 2;
        float4 v = *reinterpret_cast<const float4*>(Sb + (size_t)m*256 + k4);
        Ssm[(k4+0)*65 + m] = v.x;
        Ssm[(k4+1)*65 + m] = v.y;
        Ssm[(k4+2)*65 + m] = v.z;
        Ssm[(k4+3)*65 + m] = v.w;
    }

    unsigned long long acc2[8][4];
    #pragma unroll
    for (int i = 0; i < 8; i++)
        #pragma unroll
        for (int j = 0; j < 4; j++) acc2[i][j] = 0ull;

    const float* Ab = g_A + (size_t)b*NN*DD;  // [n][h]

    for (int k0 = 0; k0 < 256; k0 += 32) {
        __syncthreads();
        // load A chunk transposed: Asm[kk][n]
        #pragma unroll
        for (int idx = tid; idx < 256*32; idx += 256) {
            int n = idx >> 5, kk = idx & 31;
            Asm[kk*260 + n] = Ab[n*256 + k0 + kk];
        }
        __syncthreads();
        #pragma unroll 8
        for (int kk = 0; kk < 32; kk++) {
            const float* Ar = Asm + kk*260 + lane*8;
            ulonglong2 t0 = *reinterpret_cast<const ulonglong2*>(Ar);
            ulonglong2 t1 = *reinterpret_cast<const ulonglong2*>(Ar + 4);
            unsigned long long a2[4] = {t0.x, t0.y, t1.x, t1.y};
            const float* Sk = Ssm + (k0 + kk)*65 + w*8;
            #pragma unroll
            for (int i = 0; i < 8; i++) {
                unsigned long long s2 = pack2(Sk[i]);   // broadcast LDS
                fma2(acc2[i][0], s2, a2[0]);
                fma2(acc2[i][1], s2, a2[1]);
                fma2(acc2[i][2], s2, a2[2]);
                fma2(acc2[i][3], s2, a2[3]);
            }
        }
    }

    // unpack accumulators
    float acc[8][8];
    #pragma unroll
    for (int i = 0; i < 8; i++)
        #pragma unroll
        for (int j = 0; j < 4; j++) {
            float2 v = unpack2(acc2[i][j]);
            acc[i][2*j] = v.x; acc[i][2*j+1] = v.y;
        }

    // epilogue: + c[n] + mask2d[m], relu, normalize over n, store P
    float cv[8];
    #pragma unroll
    for (int j = 0; j < 8; j++) cv[j] = g_c[b*NN + lane*8 + j];
    const float* amb = am + b*NN;
    #pragma unroll
    for (int i = 0; i < 8; i++) {
        int mg = m0 + w*8 + i;
        float mv = amb[mg >> 8] * amb[mg & 255];
        float rs = 0.f;
        #pragma unroll
        for (int j = 0; j < 8; j++) {
            float v = fmaxf(acc[i][j] + cv[j] + mv, 0.f);
            acc[i][j] = v;
            rs += v;
        }
        #pragma unroll
        for (int of = 16; of > 0; of >>= 1) rs += __shfl_xor_sync(0xffffffffu, rs, of);
        float inv = 1.f / (rs + 2.56e-10f);   // sum(p + 1e-12) over 256
        float4 o0, o1;
        o0.x = acc[i][0]*inv; o0.y = acc[i][1]*inv; o0.z = acc[i][2]*inv; o0.w = acc[i][3]*inv;
        o1.x = acc[i][4]*inv; o1.y = acc[i][5]*inv; o1.z = acc[i][6]*inv; o1.w = acc[i][7]*inv;
        size_t po = ((size_t)b*M_PER_B + mg)*256 + lane*8;
        *reinterpret_cast<float4*>(g_P + po)     = o0;
        *reinterpret_cast<float4*>(g_P + po + 4) = o1;
    }
}

// =====================================================================
// Kernel 3 (pass B): G_partial[nslice, h] = sum_{m in chunk} P[m,n] S[m,h]
//                    and t_partial[n] = sum_m P[m,n].   FFMA2 microkernel.
// grid (64 ksplit, 4 nblk, 4 b), 256 threads
// warp w -> n-local rows w*8..+8 (of 64-wide slice), lane -> h cols lane*8..+8
// =====================================================================
__global__ void __launch_bounds__(256, 2) passB_kernel(const float* __restrict__ S)
{
    __shared__ __align__(16) float Psm[32*64];
    __shared__ __align__(16) float Vsm[32*256];

    int ks = blockIdx.x, nb = blockIdx.y, b = blockIdx.z;
    int tid = threadIdx.x, lane = tid & 31, w = tid >> 5;

    unsigned long long acc2[8][4];
    #pragma unroll
    for (int i = 0; i < 8; i++)
        #pragma unroll
        for (int j = 0; j < 4; j++) acc2[i][j] = 0ull;
    float tpart = 0.f;

    const float* Sb = S   + (size_t)b*M_PER_B*256;
    const float* Pb = g_P + (size_t)b*M_PER_B*256;
    int mbase0 = ks * KCHUNK;

    for (int it = 0; it < KCHUNK/32; it++) {
        int mb = mbase0 + it*32;
        __syncthreads();
        // load P tile [32 m][64 n-slice]
        #pragma unroll
        for (int idx = tid; idx < 512; idx += 256) {
            int r = idx >> 4, n4 = (idx & 15) << 2;
            *reinterpret_cast<float4*>(&Psm[r*64 + n4]) =
                *reinterpret_cast<const float4*>(&Pb[(size_t)(mb + r)*256 + nb*64 + n4]);
        }
        // load S tile [32 m][256 h]
        #pragma unroll
        for (int idx = tid; idx < 2048; idx += 256) {
            int r = idx >> 6, h4 = (idx & 63) << 2;
            *reinterpret_cast<float4*>(&Vsm[r*256 + h4]) =
                *reinterpret_cast<const float4*>(&Sb[(size_t)(mb + r)*256 + h4]);
        }
        __syncthreads();
        if (tid < 64) {
            #pragma unroll 8
            for (int mm = 0; mm < 32; mm++) tpart += Psm[mm*64 + tid];
        }
        #pragma unroll 8
        for (int mm = 0; mm < 32; mm++) {
            const float* Vr = Vsm + mm*256 + lane*8;
            ulonglong2 t0 = *reinterpret_cast<const ulonglong2*>(Vr);
            ulonglong2 t1 = *reinterpret_cast<const ulonglong2*>(Vr + 4);
            unsigned long long sv2[4] = {t0.x, t0.y, t1.x, t1.y};
            const float* Pr = Psm + mm*64 + w*8;
            #pragma unroll
            for (int i = 0; i < 8; i++) {
                unsigned long long p2 = pack2(Pr[i]);   // broadcast LDS
                fma2(acc2[i][0], p2, sv2[0]);
                fma2(acc2[i][1], p2, sv2[1]);
                fma2(acc2[i][2], p2, sv2[2]);
                fma2(acc2[i][3], p2, sv2[3]);
            }
        }
    }

    size_t base = (((size_t)b*KSPLIT + ks)*NBLK + nb)*64;
    #pragma unroll
    for (int i = 0; i < 8; i++) {
        size_t o = (base + w*8 + i)*256 + lane*8;
        float2 v0 = unpack2(acc2[i][0]);
        float2 v1 = unpack2(acc2[i][1]);
        float2 v2 = unpack2(acc2[i][2]);
        float2 v3 = unpack2(acc2[i][3]);
        float4 o0, o1;
        o0.x = v0.x; o0.y = v0.y; o0.z = v1.x; o0.w = v1.y;
        o1.x = v2.x; o1.y = v2.y; o1.z = v3.x; o1.w = v3.y;
        *reinterpret_cast<float4*>(g_W + o)     = o0;
        *reinterpret_cast<float4*>(g_W + o + 4) = o1;
    }
    if (tid < 64) g_Wt[base + tid] = tpart;
}

// =====================================================================
// Kernel 4: reduce split-K -> G row, t ; context = G@Wv + t*bv ;
//           out = context@Wo + bo ; y = LN(out + hidden)
// grid (256 n, 4 b), 256 threads
// =====================================================================
__global__ void __launch_bounds__(256) final_kernel(
    const float* __restrict__ hidden,
    const float* __restrict__ Wv, const float* __restrict__ bv,
    const float* __restrict__ Wo, const float* __restrict__ bo,
    const float* __restrict__ gamma, const float* __restrict__ beta,
    float* __restrict__ out)
{
    int n = blockIdx.x, b = blockIdx.y, t = threadIdx.x;
    __shared__ float grow[256];
    __shared__ float crow[256];
    __shared__ float red[64];
    __shared__ float wsum[8];

    int nb = n >> 6, nl = n & 63;
    float g = 0.f;
    #pragma unroll 8
    for (int ks = 0; ks < KSPLIT; ks++)
        g += g_W[((((size_t)b*KSPLIT + ks)*NBLK + nb)*64 + nl)*256 + t];
    grow[t] = g;
    if (t < 64)
        red[t] = g_Wt[(((size_t)b*KSPLIT + t)*NBLK + nb)*64 + nl];
    __syncthreads();

    float tsum = 0.f;
    #pragma unroll
    for (int i = 0; i < 64; i++) tsum += red[i];

    // context_d = sum_h G[n,h] Wv[h][d] + tsum*bv[d]
    float c = tsum * bv[t];
    #pragma unroll 8
    for (int h = 0; h < 256; h++) c += grow[h] * Wv[h*256 + t];
    crow[t] = c;
    __syncthreads();

    // out_h = sum_d c[d] Wo[d][h] + bo[h]
    float o = bo[t];
    #pragma unroll 8
    for (int d = 0; d < 256; d++) o += crow[d] * Wo[d*256 + t];
    float x = o + hidden[(b*256 + n)*256 + t];

    // LayerNorm over 256 (block-wide)
    int lane = t & 31, w = t >> 5;
    float s = x;
    #pragma unroll
    for (int of = 16; of > 0; of >>= 1) s += __shfl_xor_sync(0xffffffffu, s, of);
    if (lane == 0) wsum[w] = s;
    __syncthreads();
    float tot = 0.f;
    #pragma unroll
    for (int i = 0; i < 8; i++) tot += wsum[i];
    float mean = tot * (1.f/256.f);
    float dx = x - mean;
    __syncthreads();

    float s2 = dx * dx;
    #pragma unroll
    for (int of = 16; of > 0; of >>= 1) s2 += __shfl_xor_sync(0xffffffffu, s2, of);
    if (lane == 0) wsum[w] = s2;
    __syncthreads();
    float tot2 = 0.f;
    #pragma unroll
    for (int i = 0; i < 8; i++) tot2 += wsum[i];
    float var = tot2 * (1.f/256.f);

    out[(b*256 + n)*256 + t] = gamma[t] * dx * rsqrtf(var + 1e-5f) + beta[t];
}

// =====================================================================
extern "C" void kernel_launch(void* const* d_in, const int* in_sizes, int n_in,
                              void* d_out, int out_size)
{
    const float* hidden = (const float*)d_in[0];
    const float* S      = (const float*)d_in[1];
    const float* am     = (const float*)d_in[2];
    const float* Wq     = (const float*)d_in[3];
    const float* bq     = (const float*)d_in[4];
    const float* Wk     = (const float*)d_in[5];
    const float* bk     = (const float*)d_in[6];
    const float* Wv     = (const float*)d_in[7];
    const float* bv     = (const float*)d_in[8];
    const float* Wo     = (const float*)d_in[9];
    const float* bo     = (const float*)d_in[10];
    const float* gamma  = (const float*)d_in[11];
    const float* beta   = (const float*)d_in[12];
    float* out          = (float*)d_out;

    const int smemA = (256*65 + 32*260) * sizeof(float);  // 99840 B
    cudaFuncSetAttribute(passA_kernel, cudaFuncAttributeMaxDynamicSharedMemorySize, smemA);

    prep_kernel<<<dim3(256, 4), 256>>>(hidden, Wq, bq, Wk, bk);
    passA_kernel<<<dim3(M_PER_B/TILE_M, 4), 256, smemA>>>(S, am);
    passB_kernel<<<dim3(KSPLIT, NBLK, 4), 256>>>(S);
    final_kernel<<<dim3(256, 4), 256>>>(hidden, Wv, bv, Wo, bo, gamma, beta, out);
}

// round 6
// speedup vs baseline: 2.2356x; 2.1770x over previous
#include <cuda_runtime.h>
#include <cstdint>

#define BB 4
#define M_PER_B 65536
#define KS_B 64

// ---- device scratch (static: allocation-free) ----
__device__ float g_A[BB*256*256];                  // A[b][n][h] (incl 1/16)
__device__ float g_c[BB*256];                      // bq.k_n/16
__device__ float g_P[(size_t)BB*M_PER_B*256];      // P [b][m][n]  (256 MiB)
__device__ float g_W[(size_t)BB*KS_B*2*128*256];   // split-K partials of G (64 MiB)
__device__ float g_Wt[BB*KS_B*2*128];              // split-K partials of t[n]

// ---- tf32 helpers (baseline sm_80+ PTX: legal under compute_103) ----
__device__ __forceinline__ float to_tf32(float x) {
    float r; asm("cvt.rna.tf32.f32 %0, %1;" : "=f"(r) : "f"(x)); return r;
}
__device__ __forceinline__ void mma8(float* d,
                                     uint32_t a0, uint32_t a1, uint32_t a2, uint32_t a3,
                                     uint32_t b0, uint32_t b1) {
    asm volatile("mma.sync.aligned.m16n8k8.row.col.f32.tf32.tf32.f32 "
        "{%0,%1,%2,%3}, {%4,%5,%6,%7}, {%8,%9}, {%0,%1,%2,%3};"
        : "+f"(d[0]), "+f"(d[1]), "+f"(d[2]), "+f"(d[3])
        : "r"(a0), "r"(a1), "r"(a2), "r"(a3), "r"(b0), "r"(b1));
}

// =====================================================================
// Kernel 1: K = hidden@Wk + bk ; A[b][n][h] = (Wq[h,:].K[b,n,:])/16 ;
//           c[b][n] = (bq . K[b,n,:])/16
// =====================================================================
__global__ void __launch_bounds__(256) prep_kernel(
    const float* __restrict__ hidden,
    const float* __restrict__ Wq, const float* __restrict__ bq,
    const float* __restrict__ Wk, const float* __restrict__ bk)
{
    int n = blockIdx.x, b = blockIdx.y, t = threadIdx.x;
    __shared__ float hrow[256];
    __shared__ float krow[256];
    hrow[t] = hidden[(b*256 + n)*256 + t];
    __syncthreads();

    float a = bk[t];
    #pragma unroll 8
    for (int h = 0; h < 256; h++) a += hrow[h] * Wk[h*256 + t];
    krow[t] = a;
    __syncthreads();

    int lane = t & 31, w = t >> 5;
    const float sc = 0.0625f;
    for (int h = w; h < 256; h += 8) {
        float s = 0.f;
        #pragma unroll 4
        for (int d = lane; d < 256; d += 32) s += Wq[h*256 + d] * krow[d];
        #pragma unroll
        for (int of = 16; of > 0; of >>= 1) s += __shfl_xor_sync(0xffffffffu, s, of);
        if (lane == 0) g_A[(b*256 + n)*256 + h] = s * sc;
    }
    if (w == 0) {
        float s = 0.f;
        #pragma unroll 4
        for (int d = lane; d < 256; d += 32) s += bq[d] * krow[d];
        #pragma unroll
        for (int of = 16; of > 0; of >>= 1) s += __shfl_xor_sync(0xffffffffu, s, of);
        if (lane == 0) g_c[b*256 + n] = s * sc;
    }
}

// =====================================================================
// passA: scores = S@A^T (tf32 mma.sync), +c+mask, relu, row-normalize,
//        write P[b][m][n]. CTA: 128 m x 256 n, K=256 in chunks of 32.
// 8 warps; warp w: m rows [w*16, w*16+16), full n. acc = 128 fp32/thread.
// smem: Ssm[128][36] | Asm[256][36]  (overlaid after K loop: st[64][264]),
//       csm[256] at float offset 16896.
// =====================================================================
__global__ void __launch_bounds__(256, 1) passA_kernel(
    const float* __restrict__ S, const float* __restrict__ am)
{
    extern __shared__ float sh[];
    float* Ssm = sh;                 // 128*36 = 4608 floats
    float* Asm = sh + 4608;          // 256*36 = 9216 floats (end 13824)
    float* st  = sh;                 // staging 64*264 = 16896 floats
    float* csm = sh + 16896;         // 256 floats
    const uint32_t* Ssu = (const uint32_t*)Ssm;
    const uint32_t* Asu = (const uint32_t*)Asm;

    const int tid = threadIdx.x, lane = tid & 31, w = tid >> 5;
    const int b = blockIdx.y;
    const int m0 = blockIdx.x * 128;

    csm[tid] = g_c[b*256 + tid];

    const float* Sb = S + ((size_t)b*M_PER_B + m0)*256;
    const float* Ab = g_A + b*65536;

    float acc[128];
    #pragma unroll
    for (int i = 0; i < 128; i++) acc[i] = 0.f;

    for (int kc = 0; kc < 8; kc++) {
        int k0 = kc*32;
        __syncthreads();
        // S tile: 128 rows x 32 k (pad 36)
        #pragma unroll
        for (int i = 0; i < 4; i++) {
            int idx = i*256 + tid;
            int r = idx >> 3, c = (idx & 7) << 2;
            float4 v = *(const float4*)(Sb + (size_t)r*256 + k0 + c);
            float* d = Ssm + r*36 + c;
            d[0] = to_tf32(v.x); d[1] = to_tf32(v.y);
            d[2] = to_tf32(v.z); d[3] = to_tf32(v.w);
        }
        // A tile: 256 rows x 32 k (pad 36)
        #pragma unroll
        for (int i = 0; i < 8; i++) {
            int idx = i*256 + tid;
            int r = idx >> 3, c = (idx & 7) << 2;
            float4 v = *(const float4*)(Ab + r*256 + k0 + c);
            float* d = Asm + r*36 + c;
            d[0] = to_tf32(v.x); d[1] = to_tf32(v.y);
            d[2] = to_tf32(v.z); d[3] = to_tf32(v.w);
        }
        __syncthreads();
        #pragma unroll
        for (int ks = 0; ks < 4; ks++) {
            int kk = ks*8 + (lane & 3);
            int ar = (w*16 + (lane >> 2))*36;
            uint32_t a0 = Ssu[ar + kk];
            uint32_t a1 = Ssu[ar + 8*36 + kk];
            uint32_t a2 = Ssu[ar + kk + 4];
            uint32_t a3 = Ssu[ar + 8*36 + kk + 4];
            #pragma unroll
            for (int nt = 0; nt < 32; nt++) {
                int bc = (nt*8 + (lane >> 2))*36 + kk;
                mma8(acc + nt*4, a0, a1, a2, a3, Asu[bc], Asu[bc + 4]);
            }
        }
    }

    // ---- epilogue: +c +mask, relu, row sums, normalize ----
    const float* amb = am + b*256;
    int mg0 = m0 + w*16 + (lane >> 2);
    float mv0 = amb[mg0 >> 8] * amb[mg0 & 255];
    float mv1 = amb[(mg0 + 8) >> 8] * amb[(mg0 + 8) & 255];

    float rs0 = 0.f, rs1 = 0.f;
    #pragma unroll
    for (int nt = 0; nt < 32; nt++) {
        int n0 = nt*8 + (lane & 3)*2;
        float c0 = csm[n0], c1 = csm[n0 + 1];
        float v0 = fmaxf(acc[nt*4 + 0] + c0 + mv0, 0.f);
        float v1 = fmaxf(acc[nt*4 + 1] + c1 + mv0, 0.f);
        float v2 = fmaxf(acc[nt*4 + 2] + c0 + mv1, 0.f);
        float v3 = fmaxf(acc[nt*4 + 3] + c1 + mv1, 0.f);
        acc[nt*4+0] = v0; acc[nt*4+1] = v1; acc[nt*4+2] = v2; acc[nt*4+3] = v3;
        rs0 += v0 + v1; rs1 += v2 + v3;
    }
    rs0 += __shfl_xor_sync(0xffffffffu, rs0, 1);
    rs0 += __shfl_xor_sync(0xffffffffu, rs0, 2);
    rs1 += __shfl_xor_sync(0xffffffffu, rs1, 1);
    rs1 += __shfl_xor_sync(0xffffffffu, rs1, 2);
    float inv0 = 1.f / (rs0 + 2.56e-10f);   // sum(p + 1e-12) over 256
    float inv1 = 1.f / (rs1 + 2.56e-10f);

    // ---- transpose-stage (2 halves of 64 m rows), coalesced P writes ----
    for (int half = 0; half < 2; half++) {
        __syncthreads();
        if ((w >> 2) == half) {
            int rl = (w & 3)*16 + (lane >> 2);
            #pragma unroll
            for (int nt = 0; nt < 32; nt++) {
                int n0 = nt*8 + (lane & 3)*2;
                *(float2*)&st[rl*264 + n0] =
                    make_float2(acc[nt*4 + 0]*inv0, acc[nt*4 + 1]*inv0);
                *(float2*)&st[(rl + 8)*264 + n0] =
                    make_float2(acc[nt*4 + 2]*inv1, acc[nt*4 + 3]*inv1);
            }
        }
        __syncthreads();
        float* Pb = g_P + ((size_t)b*M_PER_B + m0 + half*64)*256;
        #pragma unroll
        for (int i = 0; i < 16; i++) {
            int idx = i*256 + tid;
            int r = idx >> 6, c = (idx & 63) << 2;
            *(float4*)(Pb + (size_t)r*256 + c) = *(const float4*)&st[r*264 + c];
        }
    }
}

// =====================================================================
// passB: G[n,h] partial = sum_m P[m,n] S[m,h] (tf32 mma.sync).
// CTA: 128 n x 256 h, split-K=64 over m (chunk 1024, subchunks of 32).
// A-op = P (transposed scalar LDS), B-op = S. t[n] partials from Psm.
// smem: Psm[32][132] | Ssm[32][264]  (overlaid after: st[64][264]).
// =====================================================================
__global__ void __launch_bounds__(256, 1) passB_kernel(const float* __restrict__ S)
{
    extern __shared__ float sh[];
    float* Psm = sh;                 // 32*132 = 4224 floats
    float* Ssm = sh + 4224;          // 32*264 = 8448 floats (end 12672)
    float* st  = sh;                 // staging 64*264 = 16896 floats
    const uint32_t* Psu = (const uint32_t*)Psm;
    const uint32_t* Ssu = (const uint32_t*)Ssm;

    const int tid = threadIdx.x, lane = tid & 31, w = tid >> 5;
    const int nt = blockIdx.x, ks = blockIdx.y, b = blockIdx.z;

    const float* Pb = g_P + (size_t)b*M_PER_B*256 + nt*128;
    const float* Sb = S + (size_t)b*M_PER_B*256;

    float acc[128];
    #pragma unroll
    for (int i = 0; i < 128; i++) acc[i] = 0.f;
    float tsum = 0.f;

    for (int ch = 0; ch < 32; ch++) {
        int mb = ks*1024 + ch*32;
        __syncthreads();
        // P tile: 32 m x 128 n (pad 132)
        #pragma unroll
        for (int i = 0; i < 4; i++) {
            int idx = i*256 + tid;
            int r = idx >> 5, c = (idx & 31) << 2;
            float4 v = *(const float4*)(Pb + (size_t)(mb + r)*256 + c);
            float* d = Psm + r*132 + c;
            d[0] = to_tf32(v.x); d[1] = to_tf32(v.y);
            d[2] = to_tf32(v.z); d[3] = to_tf32(v.w);
        }
        // S tile: 32 m x 256 h (pad 264)
        #pragma unroll
        for (int i = 0; i < 8; i++) {
            int idx = i*256 + tid;
            int r = idx >> 6, c = (idx & 63) << 2;
            float4 v = *(const float4*)(Sb + (size_t)(mb + r)*256 + c);
            float* d = Ssm + r*264 + c;
            d[0] = to_tf32(v.x); d[1] = to_tf32(v.y);
            d[2] = to_tf32(v.z); d[3] = to_tf32(v.w);
        }
        __syncthreads();
        if (tid < 128) {
            #pragma unroll 8
            for (int mm = 0; mm < 32; mm++) tsum += Psm[mm*132 + tid];
        }
        #pragma unroll
        for (int ks8 = 0; ks8 < 4; ks8++) {
            int kk = ks8*8 + (lane & 3);
            int an = w*16 + (lane >> 2);
            uint32_t a0 = Psu[kk*132 + an];
            uint32_t a1 = Psu[kk*132 + an + 8];
            uint32_t a2 = Psu[(kk + 4)*132 + an];
            uint32_t a3 = Psu[(kk + 4)*132 + an + 8];
            #pragma unroll
            for (int ht = 0; ht < 32; ht++) {
                int hc = ht*8 + (lane >> 2);
                mma8(acc + ht*4, a0, a1, a2, a3,
                     Ssu[kk*264 + hc], Ssu[(kk + 4)*264 + hc]);
            }
        }
    }

    // ---- stage + coalesced partial writes ----
    float* Wb = g_W + ((((size_t)b*KS_B + ks)*2 + nt)*128)*256;
    for (int half = 0; half < 2; half++) {
        __syncthreads();
        if ((w >> 2) == half) {
            int rl = (w & 3)*16 + (lane >> 2);
            #pragma unroll
            for (int ht = 0; ht < 32; ht++) {
                int h0 = ht*8 + (lane & 3)*2;
                *(float2*)&st[rl*264 + h0] =
                    make_float2(acc[ht*4 + 0], acc[ht*4 + 1]);
                *(float2*)&st[(rl + 8)*264 + h0] =
                    make_float2(acc[ht*4 + 2], acc[ht*4 + 3]);
            }
        }
        __syncthreads();
        #pragma unroll
        for (int i = 0; i < 16; i++) {
            int idx = i*256 + tid;
            int r = idx >> 6, c = (idx & 63) << 2;
            *(float4*)(Wb + (size_t)(half*64 + r)*256 + c) = *(const float4*)&st[r*264 + c];
        }
    }
    if (tid < 128) g_Wt[(((size_t)b*KS_B + ks)*2 + nt)*128 + tid] = tsum;
}

// =====================================================================
// Kernel 4: reduce split-K; context = G@Wv + t*bv ; out = context@Wo + bo ;
//           y = LN(out + hidden)
// =====================================================================
__global__ void __launch_bounds__(256) final_kernel(
    const float* __restrict__ hidden,
    const float* __restrict__ Wv, const float* __restrict__ bv,
    const float* __restrict__ Wo, const float* __restrict__ bo,
    const float* __restrict__ gamma, const float* __restrict__ beta,
    float* __restrict__ out)
{
    int n = blockIdx.x, b = blockIdx.y, t = threadIdx.x;
    __shared__ float grow[256];
    __shared__ float crow[256];
    __shared__ float red[KS_B];
    __shared__ float wsum[8];

    int nt = n >> 7, nl = n & 127;
    float g = 0.f;
    #pragma unroll 8
    for (int ks = 0; ks < KS_B; ks++)
        g += g_W[((((size_t)b*KS_B + ks)*2 + nt)*128 + nl)*256 + t];
    grow[t] = g;
    if (t < KS_B)
        red[t] = g_Wt[(((size_t)b*KS_B + t)*2 + nt)*128 + nl];
    __syncthreads();

    float tsum = 0.f;
    #pragma unroll
    for (int i = 0; i < KS_B; i++) tsum += red[i];

    float c = tsum * bv[t];
    #pragma unroll 8
    for (int h = 0; h < 256; h++) c += grow[h] * Wv[h*256 + t];
    crow[t] = c;
    __syncthreads();

    float o = bo[t];
    #pragma unroll 8
    for (int d = 0; d < 256; d++) o += crow[d] * Wo[d*256 + t];
    float x = o + hidden[(b*256 + n)*256 + t];

    int lane = t & 31, w = t >> 5;
    float s = x;
    #pragma unroll
    for (int of = 16; of > 0; of >>= 1) s += __shfl_xor_sync(0xffffffffu, s, of);
    if (lane == 0) wsum[w] = s;
    __syncthreads();
    float tot = 0.f;
    #pragma unroll
    for (int i = 0; i < 8; i++) tot += wsum[i];
    float mean = tot * (1.f/256.f);
    float dx = x - mean;
    __syncthreads();

    float s2 = dx * dx;
    #pragma unroll
    for (int of = 16; of > 0; of >>= 1) s2 += __shfl_xor_sync(0xffffffffu, s2, of);
    if (lane == 0) wsum[w] = s2;
    __syncthreads();
    float tot2 = 0.f;
    #pragma unroll
    for (int i = 0; i < 8; i++) tot2 += wsum[i];
    float var = tot2 * (1.f/256.f);

    out[(b*256 + n)*256 + t] = gamma[t] * dx * rsqrtf(var + 1e-5f) + beta[t];
}

// =====================================================================
extern "C" void kernel_launch(void* const* d_in, const int* in_sizes, int n_in,
                              void* d_out, int out_size)
{
    const float* hidden = (const float*)d_in[0];
    const float* S      = (const float*)d_in[1];
    const float* am     = (const float*)d_in[2];
    const float* Wq     = (const float*)d_in[3];
    const float* bq     = (const float*)d_in[4];
    const float* Wk     = (const float*)d_in[5];
    const float* bk     = (const float*)d_in[6];
    const float* Wv     = (const float*)d_in[7];
    const float* bv     = (const float*)d_in[8];
    const float* Wo     = (const float*)d_in[9];
    const float* bo     = (const float*)d_in[10];
    const float* gamma  = (const float*)d_in[11];
    const float* beta   = (const float*)d_in[12];
    float* out          = (float*)d_out;

    const int smemA = (16896 + 256) * 4;   // staging(64x264) + csm = 68608 B
    const int smemB = 16896 * 4;           // staging(64x264)       = 67584 B
    cudaFuncSetAttribute(passA_kernel, cudaFuncAttributeMaxDynamicSharedMemorySize, smemA);
    cudaFuncSetAttribute(passB_kernel, cudaFuncAttributeMaxDynamicSharedMemorySize, smemB);

    prep_kernel<<<dim3(256, 4), 256>>>(hidden, Wq, bq, Wk, bk);
    passA_kernel<<<dim3(M_PER_B/128, 4), 256, smemA>>>(S, am);
    passB_kernel<<<dim3(2, KS_B, 4), 256, smemB>>>(S);
    final_kernel<<<dim3(256, 4), 256>>>(hidden, Wv, bv, Wo, bo, gamma, beta, out);
}

// round 7
// speedup vs baseline: 2.6598x; 1.1897x over previous
#include <cuda_runtime.h>
#include <cstdint>

#define BB 4
#define M_PER_B 65536
#define KS_B 64

// ---- device scratch (static: allocation-free) ----
__device__ float g_A[BB*256*256];                  // A[b][n][h] (incl 1/16)
__device__ float g_c[BB*256];                      // bq.k_n/16
__device__ float g_P[(size_t)BB*256*M_PER_B];      // P^T [b][n][m]  (256 MiB)
__device__ float g_W[(size_t)BB*KS_B*2*128*256];   // split-K partials of G
__device__ float g_Wt[BB*KS_B*2*128];              // split-K partials of t[n]

// ---- helpers ----
__device__ __forceinline__ uint32_t smem_u32(const void* p) {
    return (uint32_t)__cvta_generic_to_shared(p);
}
__device__ __forceinline__ void cp16(uint32_t dst, const void* src) {
    asm volatile("cp.async.cg.shared.global [%0], [%1], 16;" :: "r"(dst), "l"(src));
}
#define CP_COMMIT() asm volatile("cp.async.commit_group;" ::: "memory")
#define CP_WAIT0()  asm volatile("cp.async.wait_group 0;" ::: "memory")
#define CP_WAIT1()  asm volatile("cp.async.wait_group 1;" ::: "memory")

__device__ __forceinline__ uint32_t ldcvt(const float* p) {
    float r;
    asm("cvt.rna.tf32.f32 %0, %1;" : "=f"(r) : "f"(*p));
    return __float_as_uint(r);
}
__device__ __forceinline__ void mma8(float* d,
                                     uint32_t a0, uint32_t a1, uint32_t a2, uint32_t a3,
                                     uint32_t b0, uint32_t b1) {
    asm volatile("mma.sync.aligned.m16n8k8.row.col.f32.tf32.tf32.f32 "
        "{%0,%1,%2,%3}, {%4,%5,%6,%7}, {%8,%9}, {%0,%1,%2,%3};"
        : "+f"(d[0]), "+f"(d[1]), "+f"(d[2]), "+f"(d[3])
        : "r"(a0), "r"(a1), "r"(a2), "r"(a3), "r"(b0), "r"(b1));
}

// =====================================================================
// Kernel 1: K = hidden@Wk + bk ; A[b][n][h] = (Wq[h,:].K[b,n,:])/16 ;
//           c[b][n] = (bq . K[b,n,:])/16
// =====================================================================
__global__ void __launch_bounds__(256) prep_kernel(
    const float* __restrict__ hidden,
    const float* __restrict__ Wq, const float* __restrict__ bq,
    const float* __restrict__ Wk, const float* __restrict__ bk)
{
    int n = blockIdx.x, b = blockIdx.y, t = threadIdx.x;
    __shared__ float hrow[256];
    __shared__ float krow[256];
    hrow[t] = hidden[(b*256 + n)*256 + t];
    __syncthreads();

    float a = bk[t];
    #pragma unroll 8
    for (int h = 0; h < 256; h++) a += hrow[h] * Wk[h*256 + t];
    krow[t] = a;
    __syncthreads();

    int lane = t & 31, w = t >> 5;
    const float sc = 0.0625f;
    for (int h = w; h < 256; h += 8) {
        float s = 0.f;
        #pragma unroll 4
        for (int d = lane; d < 256; d += 32) s += Wq[h*256 + d] * krow[d];
        #pragma unroll
        for (int of = 16; of > 0; of >>= 1) s += __shfl_xor_sync(0xffffffffu, s, of);
        if (lane == 0) g_A[(b*256 + n)*256 + h] = s * sc;
    }
    if (w == 0) {
        float s = 0.f;
        #pragma unroll 4
        for (int d = lane; d < 256; d += 32) s += bq[d] * krow[d];
        #pragma unroll
        for (int of = 16; of > 0; of >>= 1) s += __shfl_xor_sync(0xffffffffu, s, of);
        if (lane == 0) g_c[b*256 + n] = s * sc;
    }
}

// =====================================================================
// passA: scores = S@A^T (tf32 mma.sync), +c+mask, relu, row-normalize,
//        write P^T[b][n][m]. CTA: 128 m x 256 n, K=256, 8 chunks of 32,
//        cp.async double-buffered. Warps: 4 m-groups(32) x 2 n-groups(128).
// smem (floats): buf[2]{ S[128][36], A[256][36] } = 27648 ; csm@27648 ;
//                rsum[2][128]@27904 ; staging st[128][132] overlays buf.
// =====================================================================
__global__ void __launch_bounds__(256, 1) passA_kernel(
    const float* __restrict__ S, const float* __restrict__ am)
{
    extern __shared__ float sh[];
    float* csm  = sh + 27648;
    float* rsum = sh + 27904;

    const int tid = threadIdx.x, lane = tid & 31, w = tid >> 5;
    const int mg = w >> 1, ng = w & 1;
    const int r = lane >> 2, q = lane & 3;
    const int b = blockIdx.y;
    const int m0 = blockIdx.x * 128;

    csm[tid] = g_c[b*256 + tid];

    const float* Sb = S + ((size_t)b*M_PER_B + m0)*256;
    const float* Ab = g_A + b*65536;

    float acc[128];
    #pragma unroll
    for (int i = 0; i < 128; i++) acc[i] = 0.f;

    // ---- copy chunk kc into stage st ----
    auto copy_chunk = [&](int kc, int stage) {
        int k0 = kc * 32;
        uint32_t sdst = smem_u32(sh + stage*13824);
        #pragma unroll
        for (int i = 0; i < 4; i++) {
            int seg = i*256 + tid;
            int row = seg >> 3, c = (seg & 7) << 2;
            cp16(sdst + (uint32_t)(row*36 + c)*4, Sb + (size_t)row*256 + k0 + c);
        }
        uint32_t adst = sdst + 4608u*4;
        #pragma unroll
        for (int i = 0; i < 8; i++) {
            int seg = i*256 + tid;
            int row = seg >> 3, c = (seg & 7) << 2;
            cp16(adst + (uint32_t)(row*36 + c)*4, Ab + row*256 + k0 + c);
        }
    };

    copy_chunk(0, 0);
    CP_COMMIT();

    for (int kc = 0; kc < 8; kc++) {
        __syncthreads();                 // prior compute done before overwrite
        if (kc + 1 < 8) { copy_chunk(kc + 1, (kc + 1) & 1); CP_COMMIT(); CP_WAIT1(); }
        else            { CP_WAIT0(); }
        __syncthreads();                 // chunk kc visible to all

        const float* Ss = sh + (kc & 1)*13824;
        const float* As = Ss + 4608;
        #pragma unroll
        for (int ks = 0; ks < 4; ks++) {
            int kk0 = ks*8 + q;
            uint32_t af[2][4];
            #pragma unroll
            for (int mt = 0; mt < 2; mt++) {
                const float* ap = Ss + (mg*32 + mt*16 + r)*36;
                af[mt][0] = ldcvt(ap + kk0);
                af[mt][1] = ldcvt(ap + 8*36 + kk0);
                af[mt][2] = ldcvt(ap + kk0 + 4);
                af[mt][3] = ldcvt(ap + 8*36 + kk0 + 4);
            }
            const float* bp = As + (ng*128 + r)*36 + kk0;
            #pragma unroll
            for (int nt = 0; nt < 16; nt++) {
                uint32_t b0 = ldcvt(bp + nt*8*36);
                uint32_t b1 = ldcvt(bp + nt*8*36 + 4);
                mma8(acc + nt*4,      af[0][0], af[0][1], af[0][2], af[0][3], b0, b1);
                mma8(acc + 64 + nt*4, af[1][0], af[1][1], af[1][2], af[1][3], b0, b1);
            }
        }
    }

    // ---- epilogue: +c +mask, relu, row sums over 256 n, normalize ----
    const float* amb = am + b*256;
    float mv[2][2], rs[2][2];
    #pragma unroll
    for (int mt = 0; mt < 2; mt++)
        #pragma unroll
        for (int h = 0; h < 2; h++) {
            int mgl = m0 + mg*32 + mt*16 + h*8 + r;
            mv[mt][h] = amb[mgl >> 8] * amb[mgl & 255];
            rs[mt][h] = 0.f;
        }
    #pragma unroll
    for (int nt = 0; nt < 16; nt++) {
        float c0 = csm[ng*128 + nt*8 + q*2];
        float c1 = csm[ng*128 + nt*8 + q*2 + 1];
        #pragma unroll
        for (int mt = 0; mt < 2; mt++) {
            float* a4 = acc + mt*64 + nt*4;
            float v0 = fmaxf(a4[0] + c0 + mv[mt][0], 0.f);
            float v1 = fmaxf(a4[1] + c1 + mv[mt][0], 0.f);
            float v2 = fmaxf(a4[2] + c0 + mv[mt][1], 0.f);
            float v3 = fmaxf(a4[3] + c1 + mv[mt][1], 0.f);
            a4[0] = v0; a4[1] = v1; a4[2] = v2; a4[3] = v3;
            rs[mt][0] += v0 + v1; rs[mt][1] += v2 + v3;
        }
    }
    #pragma unroll
    for (int mt = 0; mt < 2; mt++)
        #pragma unroll
        for (int h = 0; h < 2; h++) {
            rs[mt][h] += __shfl_xor_sync(0xffffffffu, rs[mt][h], 1);
            rs[mt][h] += __shfl_xor_sync(0xffffffffu, rs[mt][h], 2);
        }
    __syncthreads();   // all compute done (also protects st overlay later)
    if (q == 0) {
        #pragma unroll
        for (int mt = 0; mt < 2; mt++)
            #pragma unroll
            for (int h = 0; h < 2; h++)
                rsum[ng*128 + mg*32 + mt*16 + h*8 + r] = rs[mt][h];
    }
    __syncthreads();
    if (tid < 128) {
        float s = rsum[tid] + rsum[128 + tid];
        rsum[tid] = 1.f / (s + 2.56e-10f);   // sum(p + 1e-12) over 256
    }
    __syncthreads();
    #pragma unroll
    for (int mt = 0; mt < 2; mt++)
        #pragma unroll
        for (int h = 0; h < 2; h++) {
            float inv = rsum[mg*32 + mt*16 + h*8 + r];
            #pragma unroll
            for (int nt = 0; nt < 16; nt++) {
                acc[mt*64 + nt*4 + 2*h]     *= inv;
                acc[mt*64 + nt*4 + 2*h + 1] *= inv;
            }
        }

    // ---- transpose-stage by n-half, write P^T[b][n][m] coalesced ----
    float* st = sh;   // [128 n][132]
    for (int half = 0; half < 2; half++) {
        __syncthreads();
        if (ng == half) {
            #pragma unroll
            for (int nt = 0; nt < 16; nt++)
                #pragma unroll
                for (int mt = 0; mt < 2; mt++) {
                    int nl0 = nt*8 + q*2;
                    int ml0 = mg*32 + mt*16 + r;
                    st[nl0*132 + ml0]           = acc[mt*64 + nt*4 + 0];
                    st[(nl0 + 1)*132 + ml0]     = acc[mt*64 + nt*4 + 1];
                    st[nl0*132 + ml0 + 8]       = acc[mt*64 + nt*4 + 2];
                    st[(nl0 + 1)*132 + ml0 + 8] = acc[mt*64 + nt*4 + 3];
                }
        }
        __syncthreads();
        float* Pt = g_P + ((size_t)b*256 + half*128)*M_PER_B + m0;
        #pragma unroll
        for (int i = 0; i < 16; i++) {
            int idx = i*256 + tid;
            int n = idx >> 5, c = (idx & 31) << 2;
            *(float4*)(Pt + (size_t)n*M_PER_B + c) = *(const float4*)&st[n*132 + c];
        }
    }
}

// =====================================================================
// passB: G[n,h] partial = sum_m P^T[n,m] S[m,h] (tf32 mma.sync).
// CTA: 128 n x 256 h, K = 1024 m (split-K=64), 32 chunks of 32,
// cp.async double-buffered. Warps: 4 n-groups(32) x 2 h-groups(128).
// smem (floats): buf[2]{ P[128][36], S[32][264] } = 26112 ;
//                staging st[64][264] overlays buf.
// =====================================================================
__global__ void __launch_bounds__(256, 1) passB_kernel(const float* __restrict__ S)
{
    extern __shared__ float sh[];
    const int tid = threadIdx.x, lane = tid & 31, w = tid >> 5;
    const int mg = w >> 1, ng = w & 1;
    const int r = lane >> 2, q = lane & 3;
    const int nt2 = blockIdx.x, ks = blockIdx.y, b = blockIdx.z;

    const float* Pb = g_P + ((size_t)b*256 + nt2*128)*M_PER_B;
    const float* Sb = S + (size_t)b*M_PER_B*256;

    float acc[128];
    #pragma unroll
    for (int i = 0; i < 128; i++) acc[i] = 0.f;
    float tsum = 0.f;

    auto copy_chunk = [&](int ch, int stage) {
        int mb = ks*1024 + ch*32;
        uint32_t pdst = smem_u32(sh + stage*13056);
        #pragma unroll
        for (int i = 0; i < 4; i++) {
            int seg = i*256 + tid;
            int row = seg >> 3, c = (seg & 7) << 2;
            cp16(pdst + (uint32_t)(row*36 + c)*4, Pb + (size_t)row*M_PER_B + mb + c);
        }
        uint32_t sdst = pdst + 4608u*4;
        #pragma unroll
        for (int i = 0; i < 8; i++) {
            int seg = i*256 + tid;
            int row = seg >> 6, c = (seg & 63) << 2;
            cp16(sdst + (uint32_t)(row*264 + c)*4, Sb + (size_t)(mb + row)*256 + c);
        }
    };

    copy_chunk(0, 0);
    CP_COMMIT();

    for (int ch = 0; ch < 32; ch++) {
        __syncthreads();
        if (ch + 1 < 32) { copy_chunk(ch + 1, (ch + 1) & 1); CP_COMMIT(); CP_WAIT1(); }
        else             { CP_WAIT0(); }
        __syncthreads();

        const float* Ps = sh + (ch & 1)*13056;
        const float* Ss = Ps + 4608;

        if (tid < 128) {
            #pragma unroll 8
            for (int mm = 0; mm < 32; mm++) tsum += Ps[tid*36 + mm];
        }
        #pragma unroll
        for (int ksi = 0; ksi < 4; ksi++) {
            int kk0 = ksi*8 + q;
            uint32_t af[2][4];
            #pragma unroll
            for (int mt = 0; mt < 2; mt++) {
                const float* ap = Ps + (mg*32 + mt*16 + r)*36;
                af[mt][0] = ldcvt(ap + kk0);
                af[mt][1] = ldcvt(ap + 8*36 + kk0);
                af[mt][2] = ldcvt(ap + kk0 + 4);
                af[mt][3] = ldcvt(ap + 8*36 + kk0 + 4);
            }
            const float* bp = Ss + kk0*264 + ng*128 + r;
            #pragma unroll
            for (int nt = 0; nt < 16; nt++) {
                uint32_t b0 = ldcvt(bp + nt*8);
                uint32_t b1 = ldcvt(bp + 4*264 + nt*8);
                mma8(acc + nt*4,      af[0][0], af[0][1], af[0][2], af[0][3], b0, b1);
                mma8(acc + 64 + nt*4, af[1][0], af[1][1], af[1][2], af[1][3], b0, b1);
            }
        }
    }

    // ---- stage + coalesced partial writes (halves by mg pair) ----
    float* st = sh;   // [64][264]
    float* Wb = g_W + ((((size_t)b*KS_B + ks)*2 + nt2)*128)*256;
    for (int half = 0; half < 2; half++) {
        __syncthreads();
        if ((mg >> 1) == half) {
            #pragma unroll
            for (int nt = 0; nt < 16; nt++)
                #pragma unroll
                for (int mt = 0; mt < 2; mt++) {
                    int row0 = (mg & 1)*32 + mt*16 + r;
                    int h0 = ng*128 + nt*8 + q*2;
                    *(float2*)&st[row0*264 + h0] =
                        make_float2(acc[mt*64 + nt*4 + 0], acc[mt*64 + nt*4 + 1]);
                    *(float2*)&st[(row0 + 8)*264 + h0] =
                        make_float2(acc[mt*64 + nt*4 + 2], acc[mt*64 + nt*4 + 3]);
                }
        }
        __syncthreads();
        #pragma unroll
        for (int i = 0; i < 16; i++) {
            int idx = i*256 + tid;
            int rr = idx >> 6, c = (idx & 63) << 2;
            *(float4*)(Wb + (size_t)(half*64 + rr)*256 + c) = *(const float4*)&st[rr*264 + c];
        }
    }
    if (tid < 128) g_Wt[(((size_t)b*KS_B + ks)*2 + nt2)*128 + tid] = tsum;
}

// =====================================================================
// Kernel 4: reduce split-K; context = G@Wv + t*bv ; out = context@Wo + bo ;
//           y = LN(out + hidden)
// =====================================================================
__global__ void __launch_bounds__(256) final_kernel(
    const float* __restrict__ hidden,
    const float* __restrict__ Wv, const float* __restrict__ bv,
    const float* __restrict__ Wo, const float* __restrict__ bo,
    const float* __restrict__ gamma, const float* __restrict__ beta,
    float* __restrict__ out)
{
    int n = blockIdx.x, b = blockIdx.y, t = threadIdx.x;
    __shared__ float grow[256];
    __shared__ float crow[256];
    __shared__ float red[KS_B];
    __shared__ float wsum[8];

    int nt = n >> 7, nl = n & 127;
    float g = 0.f;
    #pragma unroll 8
    for (int ks = 0; ks < KS_B; ks++)
        g += g_W[((((size_t)b*KS_B + ks)*2 + nt)*128 + nl)*256 + t];
    grow[t] = g;
    if (t < KS_B)
        red[t] = g_Wt[(((size_t)b*KS_B + t)*2 + nt)*128 + nl];
    __syncthreads();

    float tsum = 0.f;
    #pragma unroll
    for (int i = 0; i < KS_B; i++) tsum += red[i];

    float c = tsum * bv[t];
    #pragma unroll 8
    for (int h = 0; h < 256; h++) c += grow[h] * Wv[h*256 + t];
    crow[t] = c;
    __syncthreads();

    float o = bo[t];
    #pragma unroll 8
    for (int d = 0; d < 256; d++) o += crow[d] * Wo[d*256 + t];
    float x = o + hidden[(b*256 + n)*256 + t];

    int lane = t & 31, w = t >> 5;
    float s = x;
    #pragma unroll
    for (int of = 16; of > 0; of >>= 1) s += __shfl_xor_sync(0xffffffffu, s, of);
    if (lane == 0) wsum[w] = s;
    __syncthreads();
    float tot = 0.f;
    #pragma unroll
    for (int i = 0; i < 8; i++) tot += wsum[i];
    float mean = tot * (1.f/256.f);
    float dx = x - mean;
    __syncthreads();

    float s2 = dx * dx;
    #pragma unroll
    for (int of = 16; of > 0; of >>= 1) s2 += __shfl_xor_sync(0xffffffffu, s2, of);
    if (lane == 0) wsum[w] = s2;
    __syncthreads();
    float tot2 = 0.f;
    #pragma unroll
    for (int i = 0; i < 8; i++) tot2 += wsum[i];
    float var = tot2 * (1.f/256.f);

    out[(b*256 + n)*256 + t] = gamma[t] * dx * rsqrtf(var + 1e-5f) + beta[t];
}

// =====================================================================
extern "C" void kernel_launch(void* const* d_in, const int* in_sizes, int n_in,
                              void* d_out, int out_size)
{
    const float* hidden = (const float*)d_in[0];
    const float* S      = (const float*)d_in[1];
    const float* am     = (const float*)d_in[2];
    const float* Wq     = (const float*)d_in[3];
    const float* bq     = (const float*)d_in[4];
    const float* Wk     = (const float*)d_in[5];
    const float* bk     = (const float*)d_in[6];
    const float* Wv     = (const float*)d_in[7];
    const float* bv     = (const float*)d_in[8];
    const float* Wo     = (const float*)d_in[9];
    const float* bo     = (const float*)d_in[10];
    const float* gamma  = (const float*)d_in[11];
    const float* beta   = (const float*)d_in[12];
    float* out          = (float*)d_out;

    const int smemA = 28160 * 4;   // 2x13824 buf + csm 256 + rsum 256 = 112640 B
    const int smemB = 26112 * 4;   // 2x13056 buf = 104448 B
    cudaFuncSetAttribute(passA_kernel, cudaFuncAttributeMaxDynamicSharedMemorySize, smemA);
    cudaFuncSetAttribute(passB_kernel, cudaFuncAttributeMaxDynamicSharedMemorySize, smemB);

    prep_kernel<<<dim3(256, 4), 256>>>(hidden, Wq, bq, Wk, bk);
    passA_kernel<<<dim3(M_PER_B/128, 4), 256, smemA>>>(S, am);
    passB_kernel<<<dim3(2, KS_B, 4), 256, smemB>>>(S);
    final_kernel<<<dim3(256, 4), 256>>>(hidden, Wv, bv, Wo, bo, gamma, beta, out);
}

// round 8
// speedup vs baseline: 3.2035x; 1.2044x over previous
#include <cuda_runtime.h>
#include <cstdint>

#define BB 4
#define M_PER_B 65536
#define KS_B 64

// ---- device scratch (static: allocation-free) ----
__device__ float g_A[BB*256*256];                  // A[b][n][h] (incl 1/16)
__device__ float g_c[BB*256];                      // bq.k_n/16
__device__ float g_P[(size_t)BB*256*M_PER_B];      // P^T [b][n][m]  (256 MiB)
__device__ float g_W[(size_t)BB*KS_B*2*128*256];   // split-K partials of G
__device__ float g_Wt[BB*KS_B*2*128];              // split-K partials of t[n]

// ---- helpers ----
__device__ __forceinline__ uint32_t smem_u32(const void* p) {
    return (uint32_t)__cvta_generic_to_shared(p);
}
__device__ __forceinline__ void cp16(uint32_t dst, const void* src) {
    asm volatile("cp.async.cg.shared.global [%0], [%1], 16;" :: "r"(dst), "l"(src));
}
#define CP_COMMIT() asm volatile("cp.async.commit_group;" ::: "memory")
#define CP_WAIT0()  asm volatile("cp.async.wait_group 0;" ::: "memory")
#define CP_WAIT1()  asm volatile("cp.async.wait_group 1;" ::: "memory")

// pack two f32 -> f16x2 {lo, hi}
__device__ __forceinline__ uint32_t pack_h2(float lo, float hi) {
    uint32_t r;
    asm("cvt.rn.f16x2.f32 %0, %1, %2;" : "=r"(r) : "f"(hi), "f"(lo));
    return r;
}
// load contiguous f32 pair from smem, convert to f16x2
__device__ __forceinline__ uint32_t ld2cvt(const float* p) {
    float2 v = *(const float2*)p;
    return pack_h2(v.x, v.y);
}
__device__ __forceinline__ void mma16(float* d, const uint32_t* a,
                                      uint32_t b0, uint32_t b1) {
    asm volatile("mma.sync.aligned.m16n8k16.row.col.f32.f16.f16.f32 "
        "{%0,%1,%2,%3}, {%4,%5,%6,%7}, {%8,%9}, {%0,%1,%2,%3};"
        : "+f"(d[0]), "+f"(d[1]), "+f"(d[2]), "+f"(d[3])
        : "r"(a[0]), "r"(a[1]), "r"(a[2]), "r"(a[3]), "r"(b0), "r"(b1));
}

// =====================================================================
// Kernel 1: K = hidden@Wk + bk ; A[b][n][h] = (Wq[h,:].K[b,n,:])/16 ;
//           c[b][n] = (bq . K[b,n,:])/16
// =====================================================================
__global__ void __launch_bounds__(256) prep_kernel(
    const float* __restrict__ hidden,
    const float* __restrict__ Wq, const float* __restrict__ bq,
    const float* __restrict__ Wk, const float* __restrict__ bk)
{
    int n = blockIdx.x, b = blockIdx.y, t = threadIdx.x;
    __shared__ float hrow[256];
    __shared__ float krow[256];
    hrow[t] = hidden[(b*256 + n)*256 + t];
    __syncthreads();

    float a = bk[t];
    #pragma unroll 8
    for (int h = 0; h < 256; h++) a += hrow[h] * Wk[h*256 + t];
    krow[t] = a;
    __syncthreads();

    int lane = t & 31, w = t >> 5;
    const float sc = 0.0625f;
    for (int h = w; h < 256; h += 8) {
        float s = 0.f;
        #pragma unroll 4
        for (int d = lane; d < 256; d += 32) s += Wq[h*256 + d] * krow[d];
        #pragma unroll
        for (int of = 16; of > 0; of >>= 1) s += __shfl_xor_sync(0xffffffffu, s, of);
        if (lane == 0) g_A[(b*256 + n)*256 + h] = s * sc;
    }
    if (w == 0) {
        float s = 0.f;
        #pragma unroll 4
        for (int d = lane; d < 256; d += 32) s += bq[d] * krow[d];
        #pragma unroll
        for (int of = 16; of > 0; of >>= 1) s += __shfl_xor_sync(0xffffffffu, s, of);
        if (lane == 0) g_c[b*256 + n] = s * sc;
    }
}

// =====================================================================
// passA: scores = S@A^T (fp16 mma m16n8k16, fp32 acc), +c+mask, relu,
//        row-normalize, write P^T[b][n][m]. CTA: 128m x 256n, K=256,
//        8 chunks of 32, cp.async double-buffered.
// Warps: 4 m-groups(32) x 2 n-groups(128).
// smem (floats): buf[2]{ S[128][40], A[256][40] } = 30720 ; csm@30720 ;
//                rsum[2][128]@30976 ; staging st[128][132] overlays buf.
// =====================================================================
__global__ void __launch_bounds__(256, 1) passA_kernel(
    const float* __restrict__ S, const float* __restrict__ am)
{
    extern __shared__ float sh[];
    float* csm  = sh + 30720;
    float* rsum = sh + 30976;

    const int tid = threadIdx.x, lane = tid & 31, w = tid >> 5;
    const int mg = w >> 1, ng = w & 1;
    const int r = lane >> 2, q = lane & 3;
    const int b = blockIdx.y;
    const int m0 = blockIdx.x * 128;

    csm[tid] = g_c[b*256 + tid];

    const float* Sb = S + ((size_t)b*M_PER_B + m0)*256;
    const float* Ab = g_A + b*65536;

    float acc[128];
    #pragma unroll
    for (int i = 0; i < 128; i++) acc[i] = 0.f;

    auto copy_chunk = [&](int kc, int stage) {
        int k0 = kc * 32;
        uint32_t sdst = smem_u32(sh + stage*15360);
        #pragma unroll
        for (int i = 0; i < 4; i++) {
            int seg = i*256 + tid;
            int row = seg >> 3, c = (seg & 7) << 2;
            cp16(sdst + (uint32_t)(row*40 + c)*4, Sb + (size_t)row*256 + k0 + c);
        }
        uint32_t adst = sdst + 5120u*4;
        #pragma unroll
        for (int i = 0; i < 8; i++) {
            int seg = i*256 + tid;
            int row = seg >> 3, c = (seg & 7) << 2;
            cp16(adst + (uint32_t)(row*40 + c)*4, Ab + row*256 + k0 + c);
        }
    };

    copy_chunk(0, 0);
    CP_COMMIT();

    for (int kc = 0; kc < 8; kc++) {
        __syncthreads();
        if (kc + 1 < 8) { copy_chunk(kc + 1, (kc + 1) & 1); CP_COMMIT(); CP_WAIT1(); }
        else            { CP_WAIT0(); }
        __syncthreads();

        const float* Ss = sh + (kc & 1)*15360;
        const float* As = Ss + 5120;
        #pragma unroll
        for (int step = 0; step < 2; step++) {
            int kk0 = step*16 + q*2;
            uint32_t af[2][4];
            #pragma unroll
            for (int mt = 0; mt < 2; mt++) {
                const float* ap = Ss + (mg*32 + mt*16 + r)*40 + kk0;
                af[mt][0] = ld2cvt(ap);
                af[mt][1] = ld2cvt(ap + 8*40);
                af[mt][2] = ld2cvt(ap + 8);
                af[mt][3] = ld2cvt(ap + 8*40 + 8);
            }
            const float* bp = As + (ng*128 + r)*40 + kk0;
            #pragma unroll
            for (int nt = 0; nt < 16; nt++) {
                uint32_t b0 = ld2cvt(bp + nt*8*40);
                uint32_t b1 = ld2cvt(bp + nt*8*40 + 8);
                mma16(acc + nt*4,      af[0], b0, b1);
                mma16(acc + 64 + nt*4, af[1], b0, b1);
            }
        }
    }

    // ---- epilogue: +c +mask, relu, row sums over 256 n, normalize ----
    const float* amb = am + b*256;
    float mv[2][2], rs[2][2];
    #pragma unroll
    for (int mt = 0; mt < 2; mt++)
        #pragma unroll
        for (int h = 0; h < 2; h++) {
            int mgl = m0 + mg*32 + mt*16 + h*8 + r;
            mv[mt][h] = amb[mgl >> 8] * amb[mgl & 255];
            rs[mt][h] = 0.f;
        }
    #pragma unroll
    for (int nt = 0; nt < 16; nt++) {
        float c0 = csm[ng*128 + nt*8 + q*2];
        float c1 = csm[ng*128 + nt*8 + q*2 + 1];
        #pragma unroll
        for (int mt = 0; mt < 2; mt++) {
            float* a4 = acc + mt*64 + nt*4;
            float v0 = fmaxf(a4[0] + c0 + mv[mt][0], 0.f);
            float v1 = fmaxf(a4[1] + c1 + mv[mt][0], 0.f);
            float v2 = fmaxf(a4[2] + c0 + mv[mt][1], 0.f);
            float v3 = fmaxf(a4[3] + c1 + mv[mt][1], 0.f);
            a4[0] = v0; a4[1] = v1; a4[2] = v2; a4[3] = v3;
            rs[mt][0] += v0 + v1; rs[mt][1] += v2 + v3;
        }
    }
    #pragma unroll
    for (int mt = 0; mt < 2; mt++)
        #pragma unroll
        for (int h = 0; h < 2; h++) {
            rs[mt][h] += __shfl_xor_sync(0xffffffffu, rs[mt][h], 1);
            rs[mt][h] += __shfl_xor_sync(0xffffffffu, rs[mt][h], 2);
        }
    __syncthreads();
    if (q == 0) {
        #pragma unroll
        for (int mt = 0; mt < 2; mt++)
            #pragma unroll
            for (int h = 0; h < 2; h++)
                rsum[ng*128 + mg*32 + mt*16 + h*8 + r] = rs[mt][h];
    }
    __syncthreads();
    if (tid < 128) {
        float s = rsum[tid] + rsum[128 + tid];
        rsum[tid] = 1.f / (s + 2.56e-10f);   // sum(p + 1e-12) over 256
    }
    __syncthreads();
    #pragma unroll
    for (int mt = 0; mt < 2; mt++)
        #pragma unroll
        for (int h = 0; h < 2; h++) {
            float inv = rsum[mg*32 + mt*16 + h*8 + r];
            #pragma unroll
            for (int nt = 0; nt < 16; nt++) {
                acc[mt*64 + nt*4 + 2*h]     *= inv;
                acc[mt*64 + nt*4 + 2*h + 1] *= inv;
            }
        }

    // ---- transpose-stage by n-half, write P^T[b][n][m] coalesced ----
    float* st = sh;   // [128 n][132]
    for (int half = 0; half < 2; half++) {
        __syncthreads();
        if (ng == half) {
            #pragma unroll
            for (int nt = 0; nt < 16; nt++)
                #pragma unroll
                for (int mt = 0; mt < 2; mt++) {
                    int nl0 = nt*8 + q*2;
                    int ml0 = mg*32 + mt*16 + r;
                    st[nl0*132 + ml0]           = acc[mt*64 + nt*4 + 0];
                    st[(nl0 + 1)*132 + ml0]     = acc[mt*64 + nt*4 + 1];
                    st[nl0*132 + ml0 + 8]       = acc[mt*64 + nt*4 + 2];
                    st[(nl0 + 1)*132 + ml0 + 8] = acc[mt*64 + nt*4 + 3];
                }
        }
        __syncthreads();
        float* Pt = g_P + ((size_t)b*256 + half*128)*M_PER_B + m0;
        #pragma unroll
        for (int i = 0; i < 16; i++) {
            int idx = i*256 + tid;
            int n = idx >> 5, c = (idx & 31) << 2;
            *(float4*)(Pt + (size_t)n*M_PER_B + c) = *(const float4*)&st[n*132 + c];
        }
    }
}

// =====================================================================
// passB: G[n,h] partial = sum_m P^T[n,m] S[m,h] (fp16 mma m16n8k16).
// CTA: 128 n x 256 h, K = 1024 m (split-K=64), 32 chunks of 32,
// cp.async double-buffered. Warps: 4 n-groups(32) x 2 h-groups(128).
// smem (floats): buf[2]{ P[128][40], S[32][264] } = 27136 ;
//                staging st[64][264] overlays buf.
// =====================================================================
__global__ void __launch_bounds__(256, 1) passB_kernel(const float* __restrict__ S)
{
    extern __shared__ float sh[];
    const int tid = threadIdx.x, lane = tid & 31, w = tid >> 5;
    const int mg = w >> 1, ng = w & 1;
    const int r = lane >> 2, q = lane & 3;
    const int nt2 = blockIdx.x, ks = blockIdx.y, b = blockIdx.z;

    const float* Pb = g_P + ((size_t)b*256 + nt2*128)*M_PER_B;
    const float* Sb = S + (size_t)b*M_PER_B*256;

    float acc[128];
    #pragma unroll
    for (int i = 0; i < 128; i++) acc[i] = 0.f;
    float tsum = 0.f;

    auto copy_chunk = [&](int ch, int stage) {
        int mb = ks*1024 + ch*32;
        uint32_t pdst = smem_u32(sh + stage*13568);
        #pragma unroll
        for (int i = 0; i < 4; i++) {
            int seg = i*256 + tid;
            int row = seg >> 3, c = (seg & 7) << 2;
            cp16(pdst + (uint32_t)(row*40 + c)*4, Pb + (size_t)row*M_PER_B + mb + c);
        }
        uint32_t sdst = pdst + 5120u*4;
        #pragma unroll
        for (int i = 0; i < 8; i++) {
            int seg = i*256 + tid;
            int row = seg >> 6, c = (seg & 63) << 2;
            cp16(sdst + (uint32_t)(row*264 + c)*4, Sb + (size_t)(mb + row)*256 + c);
        }
    };

    copy_chunk(0, 0);
    CP_COMMIT();

    for (int ch = 0; ch < 32; ch++) {
        __syncthreads();
        if (ch + 1 < 32) { copy_chunk(ch + 1, (ch + 1) & 1); CP_COMMIT(); CP_WAIT1(); }
        else             { CP_WAIT0(); }
        __syncthreads();

        const float* Ps = sh + (ch & 1)*13568;
        const float* Ss = Ps + 5120;

        if (tid < 128) {
            #pragma unroll 8
            for (int mm = 0; mm < 32; mm++) tsum += Ps[tid*40 + mm];
        }
        #pragma unroll
        for (int step = 0; step < 2; step++) {
            int kk0 = step*16 + q*2;
            uint32_t af[2][4];
            #pragma unroll
            for (int mt = 0; mt < 2; mt++) {
                const float* ap = Ps + (mg*32 + mt*16 + r)*40 + kk0;
                af[mt][0] = ld2cvt(ap);
                af[mt][1] = ld2cvt(ap + 8*40);
                af[mt][2] = ld2cvt(ap + 8);
                af[mt][3] = ld2cvt(ap + 8*40 + 8);
            }
            const float* bp = Ss + kk0*264 + ng*128 + r;
            #pragma unroll
            for (int nt = 0; nt < 16; nt++) {
                uint32_t b0 = pack_h2(bp[nt*8],         bp[264 + nt*8]);
                uint32_t b1 = pack_h2(bp[8*264 + nt*8], bp[9*264 + nt*8]);
                mma16(acc + nt*4,      af[0], b0, b1);
                mma16(acc + 64 + nt*4, af[1], b0, b1);
            }
        }
    }

    // ---- stage + coalesced partial writes (halves by mg pair) ----
    float* st = sh;   // [64][264]
    float* Wb = g_W + ((((size_t)b*KS_B + ks)*2 + nt2)*128)*256;
    for (int half = 0; half < 2; half++) {
        __syncthreads();
        if ((mg >> 1) == half) {
            #pragma unroll
            for (int nt = 0; nt < 16; nt++)
                #pragma unroll
                for (int mt = 0; mt < 2; mt++) {
                    int row0 = (mg & 1)*32 + mt*16 + r;
                    int h0 = ng*128 + nt*8 + q*2;
                    *(float2*)&st[row0*264 + h0] =
                        make_float2(acc[mt*64 + nt*4 + 0], acc[mt*64 + nt*4 + 1]);
                    *(float2*)&st[(row0 + 8)*264 + h0] =
                        make_float2(acc[mt*64 + nt*4 + 2], acc[mt*64 + nt*4 + 3]);
                }
        }
        __syncthreads();
        #pragma unroll
        for (int i = 0; i < 16; i++) {
            int idx = i*256 + tid;
            int rr = idx >> 6, c = (idx & 63) << 2;
            *(float4*)(Wb + (size_t)(half*64 + rr)*256 + c) = *(const float4*)&st[rr*264 + c];
        }
    }
    if (tid < 128) g_Wt[(((size_t)b*KS_B + ks)*2 + nt2)*128 + tid] = tsum;
}

// =====================================================================
// Kernel 4: reduce split-K; context = G@Wv + t*bv ; out = context@Wo + bo ;
//           y = LN(out + hidden)
// =====================================================================
__global__ void __launch_bounds__(256) final_kernel(
    const float* __restrict__ hidden,
    const float* __restrict__ Wv, const float* __restrict__ bv,
    const float* __restrict__ Wo, const float* __restrict__ bo,
    const float* __restrict__ gamma, const float* __restrict__ beta,
    float* __restrict__ out)
{
    int n = blockIdx.x, b = blockIdx.y, t = threadIdx.x;
    __shared__ float grow[256];
    __shared__ float crow[256];
    __shared__ float red[KS_B];
    __shared__ float wsum[8];

    int nt = n >> 7, nl = n & 127;
    float g = 0.f;
    #pragma unroll 8
    for (int ks = 0; ks < KS_B; ks++)
        g += g_W[((((size_t)b*KS_B + ks)*2 + nt)*128 + nl)*256 + t];
    grow[t] = g;
    if (t < KS_B)
        red[t] = g_Wt[(((size_t)b*KS_B + t)*2 + nt)*128 + nl];
    __syncthreads();

    float tsum = 0.f;
    #pragma unroll
    for (int i = 0; i < KS_B; i++) tsum += red[i];

    float c = tsum * bv[t];
    #pragma unroll 8
    for (int h = 0; h < 256; h++) c += grow[h] * Wv[h*256 + t];
    crow[t] = c;
    __syncthreads();

    float o = bo[t];
    #pragma unroll 8
    for (int d = 0; d < 256; d++) o += crow[d] * Wo[d*256 + t];
    float x = o + hidden[(b*256 + n)*256 + t];

    int lane = t & 31, w = t >> 5;
    float s = x;
    #pragma unroll
    for (int of = 16; of > 0; of >>= 1) s += __shfl_xor_sync(0xffffffffu, s, of);
    if (lane == 0) wsum[w] = s;
    __syncthreads();
    float tot = 0.f;
    #pragma unroll
    for (int i = 0; i < 8; i++) tot += wsum[i];
    float mean = tot * (1.f/256.f);
    float dx = x - mean;
    __syncthreads();

    float s2 = dx * dx;
    #pragma unroll
    for (int of = 16; of > 0; of >>= 1) s2 += __shfl_xor_sync(0xffffffffu, s2, of);
    if (lane == 0) wsum[w] = s2;
    __syncthreads();
    float tot2 = 0.f;
    #pragma unroll
    for (int i = 0; i < 8; i++) tot2 += wsum[i];
    float var = tot2 * (1.f/256.f);

    out[(b*256 + n)*256 + t] = gamma[t] * dx * rsqrtf(var + 1e-5f) + beta[t];
}

// =====================================================================
extern "C" void kernel_launch(void* const* d_in, const int* in_sizes, int n_in,
                              void* d_out, int out_size)
{
    const float* hidden = (const float*)d_in[0];
    const float* S      = (const float*)d_in[1];
    const float* am     = (const float*)d_in[2];
    const float* Wq     = (const float*)d_in[3];
    const float* bq     = (const float*)d_in[4];
    const float* Wk     = (const float*)d_in[5];
    const float* bk     = (const float*)d_in[6];
    const float* Wv     = (const float*)d_in[7];
    const float* bv     = (const float*)d_in[8];
    const float* Wo     = (const float*)d_in[9];
    const float* bo     = (const float*)d_in[10];
    const float* gamma  = (const float*)d_in[11];
    const float* beta   = (const float*)d_in[12];
    float* out          = (float*)d_out;

    const int smemA = 31232 * 4;   // 2x15360 buf + csm 256 + rsum 256 = 124928 B
    const int smemB = 27136 * 4;   // 2x13568 buf = 108544 B
    cudaFuncSetAttribute(passA_kernel, cudaFuncAttributeMaxDynamicSharedMemorySize, smemA);
    cudaFuncSetAttribute(passB_kernel, cudaFuncAttributeMaxDynamicSharedMemorySize, smemB);

    prep_kernel<<<dim3(256, 4), 256>>>(hidden, Wq, bq, Wk, bk);
    passA_kernel<<<dim3(M_PER_B/128, 4), 256, smemA>>>(S, am);
    passB_kernel<<<dim3(2, KS_B, 4), 256, smemB>>>(S);
    final_kernel<<<dim3(256, 4), 256>>>(hidden, Wv, bv, Wo, bo, gamma, beta, out);
}

// round 9
// speedup vs baseline: 3.8876x; 1.2135x over previous
#include <cuda_runtime.h>
#include <cuda_fp16.h>
#include <cstdint>

#define BB 4
#define M_PER_B 65536
#define KS_B 64

// ---- device scratch (static: allocation-free) ----
__device__ float  g_c[BB*256];                      // bq.k_n/16
__device__ __half g_Ah[BB*256*256];                 // A fp16 [b][n][h] (incl 1/16)
__device__ __half g_Sh[(size_t)BB*M_PER_B*256];     // S fp16 (written by passA)
__device__ __half g_Ph[(size_t)BB*256*M_PER_B];     // P^T fp16 [b][n][m]
__device__ float  g_W[(size_t)BB*KS_B*2*128*256];   // split-K partials of G
__device__ float  g_Wt[BB*KS_B*2*128];              // split-K partials of t[n]

// ---- helpers ----
__device__ __forceinline__ uint32_t smem_u32(const void* p) {
    return (uint32_t)__cvta_generic_to_shared(p);
}
__device__ __forceinline__ void cp16(uint32_t dst, const void* src) {
    asm volatile("cp.async.cg.shared.global [%0], [%1], 16;" :: "r"(dst), "l"(src));
}
#define CP_COMMIT() asm volatile("cp.async.commit_group;" ::: "memory")
#define CP_WAIT0()  asm volatile("cp.async.wait_group 0;" ::: "memory")
#define CP_WAIT1()  asm volatile("cp.async.wait_group 1;" ::: "memory")

// pack two f32 -> f16x2 {lo, hi}
__device__ __forceinline__ uint32_t pack_h2(float lo, float hi) {
    uint32_t r;
    asm("cvt.rn.f16x2.f32 %0, %1, %2;" : "=r"(r) : "f"(hi), "f"(lo));
    return r;
}
__device__ __forceinline__ void ldm_x4(uint32_t* r, uint32_t addr) {
    asm volatile("ldmatrix.sync.aligned.m8n8.x4.shared.b16 {%0,%1,%2,%3}, [%4];"
        : "=r"(r[0]), "=r"(r[1]), "=r"(r[2]), "=r"(r[3]) : "r"(addr));
}
__device__ __forceinline__ void ldm_x4t(uint32_t* r, uint32_t addr) {
    asm volatile("ldmatrix.sync.aligned.m8n8.x4.trans.shared.b16 {%0,%1,%2,%3}, [%4];"
        : "=r"(r[0]), "=r"(r[1]), "=r"(r[2]), "=r"(r[3]) : "r"(addr));
}
__device__ __forceinline__ void mma16(float* d, const uint32_t* a,
                                      uint32_t b0, uint32_t b1) {
    asm volatile("mma.sync.aligned.m16n8k16.row.col.f32.f16.f16.f32 "
        "{%0,%1,%2,%3}, {%4,%5,%6,%7}, {%8,%9}, {%0,%1,%2,%3};"
        : "+f"(d[0]), "+f"(d[1]), "+f"(d[2]), "+f"(d[3])
        : "r"(a[0]), "r"(a[1]), "r"(a[2]), "r"(a[3]), "r"(b0), "r"(b1));
}

// =====================================================================
// Kernel 1: K = hidden@Wk + bk ; A fp16 [b][n][h] = (Wq[h,:].K[b,n,:])/16 ;
//           c[b][n] = (bq . K[b,n,:])/16
// =====================================================================
__global__ void __launch_bounds__(256) prep_kernel(
    const float* __restrict__ hidden,
    const float* __restrict__ Wq, const float* __restrict__ bq,
    const float* __restrict__ Wk, const float* __restrict__ bk)
{
    int n = blockIdx.x, b = blockIdx.y, t = threadIdx.x;
    __shared__ float hrow[256];
    __shared__ float krow[256];
    hrow[t] = hidden[(b*256 + n)*256 + t];
    __syncthreads();

    float a = bk[t];
    #pragma unroll 8
    for (int h = 0; h < 256; h++) a += hrow[h] * Wk[h*256 + t];
    krow[t] = a;
    __syncthreads();

    int lane = t & 31, w = t >> 5;
    const float sc = 0.0625f;
    for (int h = w; h < 256; h += 8) {
        float s = 0.f;
        #pragma unroll 4
        for (int d = lane; d < 256; d += 32) s += Wq[h*256 + d] * krow[d];
        #pragma unroll
        for (int of = 16; of > 0; of >>= 1) s += __shfl_xor_sync(0xffffffffu, s, of);
        if (lane == 0) g_Ah[(b*256 + n)*256 + h] = __float2half(s * sc);
    }
    if (w == 0) {
        float s = 0.f;
        #pragma unroll 4
        for (int d = lane; d < 256; d += 32) s += bq[d] * krow[d];
        #pragma unroll
        for (int of = 16; of > 0; of >>= 1) s += __shfl_xor_sync(0xffffffffu, s, of);
        if (lane == 0) g_c[b*256 + n] = s * sc;
    }
}

// =====================================================================
// passA: scores = S@A^T (fp16 mma + ldmatrix), +c+mask, relu,
//        row-normalize, write P^T fp16 and S fp16.
// CTA: 128m x 256n, K=256, 8 chunks of 32, double-buffered.
// Warps: 4 m-groups(32) x 2 n-groups(128).
// smem bytes: stage s @ s*30720: Sh fp16[128][40] (10240) + Ah fp16[256][40]
//   (20480). csm f32 @61440, rsum @62464. staging st fp16[128][136] overlays.
// =====================================================================
__global__ void __launch_bounds__(256, 1) passA_kernel(
    const float* __restrict__ S, const float* __restrict__ am)
{
    extern __shared__ char shc[];
    float* csm  = (float*)(shc + 61440);
    float* rsum = (float*)(shc + 62464);
    const uint32_t base_u = smem_u32(shc);

    const int tid = threadIdx.x, lane = tid & 31, w = tid >> 5;
    const int mg = w >> 1, ng = w & 1;
    const int r = lane >> 2, q = lane & 3;
    const int b = blockIdx.y;
    const int m0 = blockIdx.x * 128;

    csm[tid] = g_c[b*256 + tid];

    const float*  Sb  = S + ((size_t)b*M_PER_B + m0)*256;
    const __half* Abh = g_Ah + b*65536;

    float acc[128];
    #pragma unroll
    for (int i = 0; i < 128; i++) acc[i] = 0.f;

    const int srow = tid >> 1, sseg = tid & 1;
    float4 v0, v1, v2, v3;

    const uint32_t aOff = (uint32_t)(mg*32 + (lane & 15))*80 + (lane >> 4)*16;
    const uint32_t bOff = 10240u + (uint32_t)(ng*128 + (lane & 15))*80 + (lane >> 4)*16;

    // ---- chunk 0 preamble ----
    {
        const float4* sp = (const float4*)(Sb + (size_t)srow*256 + sseg*16);
        v0 = sp[0]; v1 = sp[1]; v2 = sp[2]; v3 = sp[3];
        uint32_t dst = base_u + 10240;
        #pragma unroll
        for (int i = 0; i < 4; i++) {
            int idx = i*256 + tid;
            int row = idx >> 2, c = idx & 3;
            cp16(dst + (uint32_t)row*80 + c*16, Abh + row*256 + c*8);
        }
        CP_COMMIT();
        uint4 q0 = make_uint4(pack_h2(v0.x, v0.y), pack_h2(v0.z, v0.w),
                              pack_h2(v1.x, v1.y), pack_h2(v1.z, v1.w));
        uint4 q1 = make_uint4(pack_h2(v2.x, v2.y), pack_h2(v2.z, v2.w),
                              pack_h2(v3.x, v3.y), pack_h2(v3.z, v3.w));
        *(uint4*)(shc + srow*80 + sseg*32)      = q0;
        *(uint4*)(shc + srow*80 + sseg*32 + 16) = q1;
        uint4* gp = (uint4*)(g_Sh + ((size_t)b*M_PER_B + m0 + srow)*256 + sseg*16);
        gp[0] = q0; gp[1] = q1;
        CP_WAIT0();
        __syncthreads();
    }

    for (int kc = 0; kc < 8; kc++) {
        if (kc < 7) {
            int k0 = (kc + 1)*32;
            const float4* sp = (const float4*)(Sb + (size_t)srow*256 + k0 + sseg*16);
            v0 = sp[0]; v1 = sp[1]; v2 = sp[2]; v3 = sp[3];
            uint32_t dst = base_u + ((kc + 1) & 1)*30720 + 10240;
            #pragma unroll
            for (int i = 0; i < 4; i++) {
                int idx = i*256 + tid;
                int row = idx >> 2, c = idx & 3;
                cp16(dst + (uint32_t)row*80 + c*16, Abh + row*256 + k0 + c*8);
            }
            CP_COMMIT();
        }
        uint32_t sb = base_u + (kc & 1)*30720;
        #pragma unroll
        for (int step = 0; step < 2; step++) {
            uint32_t af0[4], af1[4];
            ldm_x4(af0, sb + aOff + step*32);
            ldm_x4(af1, sb + aOff + 1280 + step*32);
            #pragma unroll
            for (int p = 0; p < 8; p++) {
                uint32_t bf[4];
                ldm_x4(bf, sb + bOff + p*1280 + step*32);
                mma16(acc + (p*2)*4,        af0, bf[0], bf[2]);
                mma16(acc + 64 + (p*2)*4,   af1, bf[0], bf[2]);
                mma16(acc + (p*2+1)*4,      af0, bf[1], bf[3]);
                mma16(acc + 64 + (p*2+1)*4, af1, bf[1], bf[3]);
            }
        }
        if (kc < 7) {
            int k0 = (kc + 1)*32;
            int stage = (kc + 1) & 1;
            uint4 q0 = make_uint4(pack_h2(v0.x, v0.y), pack_h2(v0.z, v0.w),
                                  pack_h2(v1.x, v1.y), pack_h2(v1.z, v1.w));
            uint4 q1 = make_uint4(pack_h2(v2.x, v2.y), pack_h2(v2.z, v2.w),
                                  pack_h2(v3.x, v3.y), pack_h2(v3.z, v3.w));
            *(uint4*)(shc + stage*30720 + srow*80 + sseg*32)      = q0;
            *(uint4*)(shc + stage*30720 + srow*80 + sseg*32 + 16) = q1;
            uint4* gp = (uint4*)(g_Sh + ((size_t)b*M_PER_B + m0 + srow)*256 + k0 + sseg*16);
            gp[0] = q0; gp[1] = q1;
            CP_WAIT0();
        }
        __syncthreads();
    }

    // ---- epilogue: +c +mask, relu, row sums over 256 n, normalize ----
    const float* amb = am + b*256;
    float mv[2][2], rs[2][2];
    #pragma unroll
    for (int mt = 0; mt < 2; mt++)
        #pragma unroll
        for (int h = 0; h < 2; h++) {
            int mgl = m0 + mg*32 + mt*16 + h*8 + r;
            mv[mt][h] = amb[mgl >> 8] * amb[mgl & 255];
            rs[mt][h] = 0.f;
        }
    #pragma unroll
    for (int nt = 0; nt < 16; nt++) {
        float c0 = csm[ng*128 + nt*8 + q*2];
        float c1 = csm[ng*128 + nt*8 + q*2 + 1];
        #pragma unroll
        for (int mt = 0; mt < 2; mt++) {
            float* a4 = acc + mt*64 + nt*4;
            float w0 = fmaxf(a4[0] + c0 + mv[mt][0], 0.f);
            float w1 = fmaxf(a4[1] + c1 + mv[mt][0], 0.f);
            float w2 = fmaxf(a4[2] + c0 + mv[mt][1], 0.f);
            float w3 = fmaxf(a4[3] + c1 + mv[mt][1], 0.f);
            a4[0] = w0; a4[1] = w1; a4[2] = w2; a4[3] = w3;
            rs[mt][0] += w0 + w1; rs[mt][1] += w2 + w3;
        }
    }
    #pragma unroll
    for (int mt = 0; mt < 2; mt++)
        #pragma unroll
        for (int h = 0; h < 2; h++) {
            rs[mt][h] += __shfl_xor_sync(0xffffffffu, rs[mt][h], 1);
            rs[mt][h] += __shfl_xor_sync(0xffffffffu, rs[mt][h], 2);
        }
    if (q == 0) {
        #pragma unroll
        for (int mt = 0; mt < 2; mt++)
            #pragma unroll
            for (int h = 0; h < 2; h++)
                rsum[ng*128 + mg*32 + mt*16 + h*8 + r] = rs[mt][h];
    }
    __syncthreads();
    if (tid < 128) {
        float s = rsum[tid] + rsum[128 + tid];
        rsum[tid] = 1.f / (s + 2.56e-10f);   // sum(p + 1e-12) over 256
    }
    __syncthreads();
    #pragma unroll
    for (int mt = 0; mt < 2; mt++)
        #pragma unroll
        for (int h = 0; h < 2; h++) {
            float inv = rsum[mg*32 + mt*16 + h*8 + r];
            #pragma unroll
            for (int nt = 0; nt < 16; nt++) {
                acc[mt*64 + nt*4 + 2*h]     *= inv;
                acc[mt*64 + nt*4 + 2*h + 1] *= inv;
            }
        }

    // ---- transpose-stage by n-half (fp16), write P^T coalesced ----
    __half* sth = (__half*)shc;   // [128 n][136 m pad]
    for (int half = 0; half < 2; half++) {
        __syncthreads();
        if (ng == half) {
            #pragma unroll
            for (int nt = 0; nt < 16; nt++)
                #pragma unroll
                for (int mt = 0; mt < 2; mt++) {
                    int nl0 = nt*8 + q*2;
                    int ml0 = mg*32 + mt*16 + r;
                    sth[nl0*136 + ml0]           = __float2half(acc[mt*64 + nt*4 + 0]);
                    sth[(nl0 + 1)*136 + ml0]     = __float2half(acc[mt*64 + nt*4 + 1]);
                    sth[nl0*136 + ml0 + 8]       = __float2half(acc[mt*64 + nt*4 + 2]);
                    sth[(nl0 + 1)*136 + ml0 + 8] = __float2half(acc[mt*64 + nt*4 + 3]);
                }
        }
        __syncthreads();
        #pragma unroll
        for (int i = 0; i < 8; i++) {
            int idx = i*256 + tid;
            int n = idx >> 4, c = idx & 15;
            *(uint4*)(g_Ph + ((size_t)b*256 + half*128 + n)*M_PER_B + m0 + c*8) =
                *(const uint4*)(shc + n*272 + c*16);
        }
    }
}

// =====================================================================
// passB: G[n,h] partial = sum_m P^T[n,m] S[m,h] (fp16 mma + ldmatrix).
// CTA: 128 n x 256 h, split-K=64 (1024 m), 32 chunks of 32, cp.async
// double-buffered (both operands fp16 in gmem).
// smem bytes: stage s @ s*27136: Ph fp16[128][40] (10240) + Ss fp16[32][264]
//   (16896). staging st f32[64][264] overlays.
// =====================================================================
__global__ void __launch_bounds__(256, 1) passB_kernel()
{
    extern __shared__ char shc[];
    const uint32_t base_u = smem_u32(shc);

    const int tid = threadIdx.x, lane = tid & 31, w = tid >> 5;
    const int mg = w >> 1, ng = w & 1;
    const int r = lane >> 2, q = lane & 3;
    const int nt2 = blockIdx.x, ks = blockIdx.y, b = blockIdx.z;

    const __half* Pb  = g_Ph + ((size_t)b*256 + nt2*128)*M_PER_B;
    const __half* Sbh = g_Sh + (size_t)b*M_PER_B*256;

    float acc[128];
    #pragma unroll
    for (int i = 0; i < 128; i++) acc[i] = 0.f;
    float tsum = 0.f;

    auto copy_chunk = [&](int ch, int stage) {
        int mb = ks*1024 + ch*32;
        uint32_t pd = base_u + stage*27136;
        #pragma unroll
        for (int i = 0; i < 2; i++) {
            int idx = i*256 + tid;
            int row = idx >> 2, c = idx & 3;
            cp16(pd + (uint32_t)row*80 + c*16, Pb + (size_t)row*M_PER_B + mb + c*8);
        }
        uint32_t sd = pd + 10240;
        #pragma unroll
        for (int i = 0; i < 4; i++) {
            int idx = i*256 + tid;
            int row = idx >> 5, c = idx & 31;
            cp16(sd + (uint32_t)row*528 + c*16, Sbh + (size_t)(mb + row)*256 + c*8);
        }
    };

    const uint32_t aOff = (uint32_t)(mg*32 + (lane & 15))*80 + (lane >> 4)*16;
    const uint32_t bOff = 10240u + (uint32_t)(lane & 15)*528 + ng*256 + (lane >> 4)*16;

    copy_chunk(0, 0);
    CP_COMMIT();

    for (int ch = 0; ch < 32; ch++) {
        __syncthreads();
        if (ch + 1 < 32) { copy_chunk(ch + 1, (ch + 1) & 1); CP_COMMIT(); CP_WAIT1(); }
        else             { CP_WAIT0(); }
        __syncthreads();

        uint32_t sb = base_u + (ch & 1)*27136;
        if (tid < 128) {
            const __half2* pr = (const __half2*)(shc + (ch & 1)*27136 + tid*80);
            #pragma unroll
            for (int j = 0; j < 16; j++) {
                float2 f = __half22float2(pr[j]);
                tsum += f.x + f.y;
            }
        }
        #pragma unroll
        for (int step = 0; step < 2; step++) {
            uint32_t af0[4], af1[4];
            ldm_x4(af0, sb + aOff + step*32);
            ldm_x4(af1, sb + aOff + 1280 + step*32);
            #pragma unroll
            for (int p = 0; p < 8; p++) {
                uint32_t bf[4];
                ldm_x4t(bf, sb + bOff + step*8448 + p*32);
                mma16(acc + (p*2)*4,        af0, bf[0], bf[1]);
                mma16(acc + 64 + (p*2)*4,   af1, bf[0], bf[1]);
                mma16(acc + (p*2+1)*4,      af0, bf[2], bf[3]);
                mma16(acc + 64 + (p*2+1)*4, af1, bf[2], bf[3]);
            }
        }
    }

    // ---- stage + coalesced partial writes (halves by mg pair) ----
    float* st = (float*)shc;   // [64][264]
    float* Wb = g_W + ((((size_t)b*KS_B + ks)*2 + nt2)*128)*256;
    for (int half = 0; half < 2; half++) {
        __syncthreads();
        if ((mg >> 1) == half) {
            #pragma unroll
            for (int nt = 0; nt < 16; nt++)
                #pragma unroll
                for (int mt = 0; mt < 2; mt++) {
                    int row0 = (mg & 1)*32 + mt*16 + r;
                    int h0 = ng*128 + nt*8 + q*2;
                    *(float2*)&st[row0*264 + h0] =
                        make_float2(acc[mt*64 + nt*4 + 0], acc[mt*64 + nt*4 + 1]);
                    *(float2*)&st[(row0 + 8)*264 + h0] =
                        make_float2(acc[mt*64 + nt*4 + 2], acc[mt*64 + nt*4 + 3]);
                }
        }
        __syncthreads();
        #pragma unroll
        for (int i = 0; i < 16; i++) {
            int idx = i*256 + tid;
            int rr = idx >> 6, c = (idx & 63) << 2;
            *(float4*)(Wb + (size_t)(half*64 + rr)*256 + c) = *(const float4*)&st[rr*264 + c];
        }
    }
    if (tid < 128) g_Wt[(((size_t)b*KS_B + ks)*2 + nt2)*128 + tid] = tsum;
}

// =====================================================================
// Kernel 4: reduce split-K; context = G@Wv + t*bv ; out = context@Wo + bo ;
//           y = LN(out + hidden)
// =====================================================================
__global__ void __launch_bounds__(256) final_kernel(
    const float* __restrict__ hidden,
    const float* __restrict__ Wv, const float* __restrict__ bv,
    const float* __restrict__ Wo, const float* __restrict__ bo,
    const float* __restrict__ gamma, const float* __restrict__ beta,
    float* __restrict__ out)
{
    int n = blockIdx.x, b = blockIdx.y, t = threadIdx.x;
    __shared__ float grow[256];
    __shared__ float crow[256];
    __shared__ float red[KS_B];
    __shared__ float wsum[8];

    int nt = n >> 7, nl = n & 127;
    float g = 0.f;
    #pragma unroll 8
    for (int ks = 0; ks < KS_B; ks++)
        g += g_W[((((size_t)b*KS_B + ks)*2 + nt)*128 + nl)*256 + t];
    grow[t] = g;
    if (t < KS_B)
        red[t] = g_Wt[(((size_t)b*KS_B + t)*2 + nt)*128 + nl];
    __syncthreads();

    float tsum = 0.f;
    #pragma unroll
    for (int i = 0; i < KS_B; i++) tsum += red[i];

    float c = tsum * bv[t];
    #pragma unroll 8
    for (int h = 0; h < 256; h++) c += grow[h] * Wv[h*256 + t];
    crow[t] = c;
    __syncthreads();

    float o = bo[t];
    #pragma unroll 8
    for (int d = 0; d < 256; d++) o += crow[d] * Wo[d*256 + t];
    float x = o + hidden[(b*256 + n)*256 + t];

    int lane = t & 31, w = t >> 5;
    float s = x;
    #pragma unroll
    for (int of = 16; of > 0; of >>= 1) s += __shfl_xor_sync(0xffffffffu, s, of);
    if (lane == 0) wsum[w] = s;
    __syncthreads();
    float tot = 0.f;
    #pragma unroll
    for (int i = 0; i < 8; i++) tot += wsum[i];
    float mean = tot * (1.f/256.f);
    float dx = x - mean;
    __syncthreads();

    float s2 = dx * dx;
    #pragma unroll
    for (int of = 16; of > 0; of >>= 1) s2 += __shfl_xor_sync(0xffffffffu, s2, of);
    if (lane == 0) wsum[w] = s2;
    __syncthreads();
    float tot2 = 0.f;
    #pragma unroll
    for (int i = 0; i < 8; i++) tot2 += wsum[i];
    float var = tot2 * (1.f/256.f);

    out[(b*256 + n)*256 + t] = gamma[t] * dx * rsqrtf(var + 1e-5f) + beta[t];
}

// =====================================================================
extern "C" void kernel_launch(void* const* d_in, const int* in_sizes, int n_in,
                              void* d_out, int out_size)
{
    const float* hidden = (const float*)d_in[0];
    const float* S      = (const float*)d_in[1];
    const float* am     = (const float*)d_in[2];
    const float* Wq     = (const float*)d_in[3];
    const float* bq     = (const float*)d_in[4];
    const float* Wk     = (const float*)d_in[5];
    const float* bk     = (const float*)d_in[6];
    const float* Wv     = (const float*)d_in[7];
    const float* bv     = (const float*)d_in[8];
    const float* Wo     = (const float*)d_in[9];
    const float* bo     = (const float*)d_in[10];
    const float* gamma  = (const float*)d_in[11];
    const float* beta   = (const float*)d_in[12];
    float* out          = (float*)d_out;

    const int smemA = 63488;   // 2x30720 fp16 stages + csm + rsum
    const int smemB = 67584;   // max(2x27136 stages, st f32 64x264)
    cudaFuncSetAttribute(passA_kernel, cudaFuncAttributeMaxDynamicSharedMemorySize, smemA);
    cudaFuncSetAttribute(passB_kernel, cudaFuncAttributeMaxDynamicSharedMemorySize, smemB);

    prep_kernel<<<dim3(256, 4), 256>>>(hidden, Wq, bq, Wk, bk);
    passA_kernel<<<dim3(M_PER_B/128, 4), 256, smemA>>>(S, am);
    passB_kernel<<<dim3(2, KS_B, 4), 256, smemB>>>();
    final_kernel<<<dim3(256, 4), 256>>>(hidden, Wv, bv, Wo, bo, gamma, beta, out);
}

// round 10
// speedup vs baseline: 4.1200x; 1.0598x over previous
#include <cuda_runtime.h>
#include <cuda_fp16.h>
#include <cstdint>

#define BB 4
#define M_PER_B 65536
#define KS_B 64

// ---- device scratch (static: allocation-free) ----
__device__ float  g_c[BB*256];                      // bq.k_n/16
__device__ __half g_Ah[BB*256*256];                 // A fp16 [b][n][h] (incl 1/16)
__device__ __half g_Sh[(size_t)BB*M_PER_B*256];     // S fp16 (written by passA)
__device__ __half g_Ph[(size_t)BB*256*M_PER_B];     // P^T fp16 [b][n][m]
__device__ float  g_W[(size_t)BB*KS_B*2*128*256];   // split-K partials of G
__device__ float  g_Wt[BB*KS_B*2*128];              // split-K partials of t[n]

// ---- helpers ----
__device__ __forceinline__ uint32_t smem_u32(const void* p) {
    return (uint32_t)__cvta_generic_to_shared(p);
}
__device__ __forceinline__ void cp16(uint32_t dst, const void* src) {
    asm volatile("cp.async.cg.shared.global [%0], [%1], 16;" :: "r"(dst), "l"(src));
}
#define CP_COMMIT() asm volatile("cp.async.commit_group;" ::: "memory")
#define CP_WAIT0()  asm volatile("cp.async.wait_group 0;" ::: "memory")

__device__ __forceinline__ uint32_t pack_h2(float lo, float hi) {
    uint32_t r;
    asm("cvt.rn.f16x2.f32 %0, %1, %2;" : "=r"(r) : "f"(hi), "f"(lo));
    return r;
}
__device__ __forceinline__ void ldm_x4(uint32_t* r, uint32_t addr) {
    asm volatile("ldmatrix.sync.aligned.m8n8.x4.shared.b16 {%0,%1,%2,%3}, [%4];"
        : "=r"(r[0]), "=r"(r[1]), "=r"(r[2]), "=r"(r[3]) : "r"(addr));
}
__device__ __forceinline__ void ldm_x4t(uint32_t* r, uint32_t addr) {
    asm volatile("ldmatrix.sync.aligned.m8n8.x4.trans.shared.b16 {%0,%1,%2,%3}, [%4];"
        : "=r"(r[0]), "=r"(r[1]), "=r"(r[2]), "=r"(r[3]) : "r"(addr));
}
__device__ __forceinline__ void mma16(float* d, const uint32_t* a,
                                      uint32_t b0, uint32_t b1) {
    asm volatile("mma.sync.aligned.m16n8k16.row.col.f32.f16.f16.f32 "
        "{%0,%1,%2,%3}, {%4,%5,%6,%7}, {%8,%9}, {%0,%1,%2,%3};"
        : "+f"(d[0]), "+f"(d[1]), "+f"(d[2]), "+f"(d[3])
        : "r"(a[0]), "r"(a[1]), "r"(a[2]), "r"(a[3]), "r"(b0), "r"(b1));
}

// =====================================================================
// Kernel 1: K = hidden@Wk + bk ; A fp16 [b][n][h] = (Wq[h,:].K[b,n,:])/16 ;
//           c[b][n] = (bq . K[b,n,:])/16
// =====================================================================
__global__ void __launch_bounds__(256) prep_kernel(
    const float* __restrict__ hidden,
    const float* __restrict__ Wq, const float* __restrict__ bq,
    const float* __restrict__ Wk, const float* __restrict__ bk)
{
    int n = blockIdx.x, b = blockIdx.y, t = threadIdx.x;
    __shared__ float hrow[256];
    __shared__ float krow[256];
    hrow[t] = hidden[(b*256 + n)*256 + t];
    __syncthreads();

    float a = bk[t];
    #pragma unroll 8
    for (int h = 0; h < 256; h++) a += hrow[h] * Wk[h*256 + t];
    krow[t] = a;
    __syncthreads();

    int lane = t & 31, w = t >> 5;
    const float sc = 0.0625f;
    for (int h = w; h < 256; h += 8) {
        float s = 0.f;
        #pragma unroll 4
        for (int d = lane; d < 256; d += 32) s += Wq[h*256 + d] * krow[d];
        #pragma unroll
        for (int of = 16; of > 0; of >>= 1) s += __shfl_xor_sync(0xffffffffu, s, of);
        if (lane == 0) g_Ah[(b*256 + n)*256 + h] = __float2half(s * sc);
    }
    if (w == 0) {
        float s = 0.f;
        #pragma unroll 4
        for (int d = lane; d < 256; d += 32) s += bq[d] * krow[d];
        #pragma unroll
        for (int of = 16; of > 0; of >>= 1) s += __shfl_xor_sync(0xffffffffu, s, of);
        if (lane == 0) g_c[b*256 + n] = s * sc;
    }
}

// =====================================================================
// passA: CTA 64m x 256n, occ 2. fp16 mma + ldmatrix. K=256, 8 chunks of 32,
// double-buffered. Warps: 4 m-groups(16) x 2 n-groups(128).
// smem bytes: stage s @ s*25600: Sh fp16[64][40] (5120) + Ah fp16[256][40]
//   (20480). csm f32 @51200, rsum @52224. staging sth fp16[256][72] overlays.
// =====================================================================
__global__ void __launch_bounds__(256, 2) passA_kernel(
    const float* __restrict__ S, const float* __restrict__ am)
{
    extern __shared__ char shc[];
    float* csm  = (float*)(shc + 51200);
    float* rsum = (float*)(shc + 52224);
    const uint32_t base_u = smem_u32(shc);

    const int tid = threadIdx.x, lane = tid & 31, w = tid >> 5;
    const int mg = w >> 1, ng = w & 1;
    const int r = lane >> 2, q = lane & 3;
    const int b = blockIdx.y;
    const int m0 = blockIdx.x * 64;

    csm[tid] = g_c[b*256 + tid];

    const float*  Sb  = S + ((size_t)b*M_PER_B + m0)*256;
    const __half* Abh = g_Ah + b*65536;

    float acc[64];
    #pragma unroll
    for (int i = 0; i < 64; i++) acc[i] = 0.f;

    const int srow = tid >> 2, sseg = tid & 3;   // 64 rows, 4 thr/row, 8 floats each
    float4 v0, v1;

    const uint32_t aOff = (uint32_t)(mg*16 + (lane & 15))*80 + (lane >> 4)*16;
    const uint32_t bOff = 5120u + (uint32_t)(ng*128 + (lane & 15))*80 + (lane >> 4)*16;

    // ---- chunk 0 preamble ----
    {
        const float4* sp = (const float4*)(Sb + (size_t)srow*256 + sseg*8);
        v0 = sp[0]; v1 = sp[1];
        uint32_t dst = base_u + 5120;
        #pragma unroll
        for (int i = 0; i < 4; i++) {
            int idx = i*256 + tid;
            int row = idx >> 2, c = idx & 3;
            cp16(dst + (uint32_t)row*80 + c*16, Abh + row*256 + c*8);
        }
        CP_COMMIT();
        uint4 q0 = make_uint4(pack_h2(v0.x, v0.y), pack_h2(v0.z, v0.w),
                              pack_h2(v1.x, v1.y), pack_h2(v1.z, v1.w));
        *(uint4*)(shc + srow*80 + sseg*16) = q0;
        *(uint4*)(g_Sh + ((size_t)b*M_PER_B + m0 + srow)*256 + sseg*8) = q0;
        CP_WAIT0();
        __syncthreads();
    }

    for (int kc = 0; kc < 8; kc++) {
        if (kc < 7) {
            int k0 = (kc + 1)*32;
            const float4* sp = (const float4*)(Sb + (size_t)srow*256 + k0 + sseg*8);
            v0 = sp[0]; v1 = sp[1];
            uint32_t dst = base_u + ((kc + 1) & 1)*25600 + 5120;
            #pragma unroll
            for (int i = 0; i < 4; i++) {
                int idx = i*256 + tid;
                int row = idx >> 2, c = idx & 3;
                cp16(dst + (uint32_t)row*80 + c*16, Abh + row*256 + k0 + c*8);
            }
            CP_COMMIT();
        }
        uint32_t sb = base_u + (kc & 1)*25600;
        #pragma unroll
        for (int step = 0; step < 2; step++) {
            uint32_t af[4];
            ldm_x4(af, sb + aOff + step*32);
            #pragma unroll
            for (int p = 0; p < 8; p++) {
                uint32_t bf[4];
                ldm_x4(bf, sb + bOff + p*1280 + step*32);
                mma16(acc + (p*2)*4,   af, bf[0], bf[2]);
                mma16(acc + (p*2+1)*4, af, bf[1], bf[3]);
            }
        }
        if (kc < 7) {
            int k0 = (kc + 1)*32;
            int stage = (kc + 1) & 1;
            uint4 q0 = make_uint4(pack_h2(v0.x, v0.y), pack_h2(v0.z, v0.w),
                                  pack_h2(v1.x, v1.y), pack_h2(v1.z, v1.w));
            *(uint4*)(shc + stage*25600 + srow*80 + sseg*16) = q0;
            *(uint4*)(g_Sh + ((size_t)b*M_PER_B + m0 + srow)*256 + k0 + sseg*8) = q0;
            CP_WAIT0();
        }
        __syncthreads();
    }

    // ---- epilogue: +c +mask, relu, row sums over 256 n, normalize ----
    const float* amb = am + b*256;
    float mv[2], rs[2];
    #pragma unroll
    for (int h = 0; h < 2; h++) {
        int mgl = m0 + mg*16 + h*8 + r;
        mv[h] = amb[mgl >> 8] * amb[mgl & 255];
        rs[h] = 0.f;
    }
    #pragma unroll
    for (int nt = 0; nt < 16; nt++) {
        float c0 = csm[ng*128 + nt*8 + q*2];
        float c1 = csm[ng*128 + nt*8 + q*2 + 1];
        float* a4 = acc + nt*4;
        float w0 = fmaxf(a4[0] + c0 + mv[0], 0.f);
        float w1 = fmaxf(a4[1] + c1 + mv[0], 0.f);
        float w2 = fmaxf(a4[2] + c0 + mv[1], 0.f);
        float w3 = fmaxf(a4[3] + c1 + mv[1], 0.f);
        a4[0] = w0; a4[1] = w1; a4[2] = w2; a4[3] = w3;
        rs[0] += w0 + w1; rs[1] += w2 + w3;
    }
    #pragma unroll
    for (int h = 0; h < 2; h++) {
        rs[h] += __shfl_xor_sync(0xffffffffu, rs[h], 1);
        rs[h] += __shfl_xor_sync(0xffffffffu, rs[h], 2);
    }
    if (q == 0) {
        rsum[ng*64 + mg*16 + r]     = rs[0];
        rsum[ng*64 + mg*16 + 8 + r] = rs[1];
    }
    __syncthreads();
    if (tid < 64) {
        float s = rsum[tid] + rsum[64 + tid];
        rsum[tid] = 1.f / (s + 2.56e-10f);   // sum(p + 1e-12) over 256
    }
    __syncthreads();
    {
        float inv0 = rsum[mg*16 + r];
        float inv1 = rsum[mg*16 + 8 + r];
        #pragma unroll
        for (int nt = 0; nt < 16; nt++) {
            acc[nt*4 + 0] *= inv0;
            acc[nt*4 + 1] *= inv0;
            acc[nt*4 + 2] *= inv1;
            acc[nt*4 + 3] *= inv1;
        }
    }

    // ---- transpose-stage (single round; sth fp16 [256 n][72 m]) ----
    __half* sth = (__half*)shc;
    #pragma unroll
    for (int nt = 0; nt < 16; nt++) {
        int n0 = ng*128 + nt*8 + q*2;
        int ml = mg*16 + r;
        sth[n0*72 + ml]           = __float2half(acc[nt*4 + 0]);
        sth[(n0 + 1)*72 + ml]     = __float2half(acc[nt*4 + 1]);
        sth[n0*72 + ml + 8]       = __float2half(acc[nt*4 + 2]);
        sth[(n0 + 1)*72 + ml + 8] = __float2half(acc[nt*4 + 3]);
    }
    __syncthreads();
    #pragma unroll
    for (int i = 0; i < 8; i++) {
        int idx = i*256 + tid;
        int n = idx >> 3, c = idx & 7;
        *(uint4*)(g_Ph + ((size_t)b*256 + n)*M_PER_B + m0 + c*8) =
            *(const uint4*)(shc + n*144 + c*16);
    }
}

// =====================================================================
// passB: G[n,h] partial = sum_m P^T[n,m] S[m,h]. CTA 128n x 128h, occ 2.
// grid x: (nt2*2 + ht), y: ks (split-K=64, 1024 m), z: b. 32 chunks of 32.
// Warps: 4 n-groups(32) x 2 h-groups(64).
// smem bytes: stage s @ s*18944: Ph fp16[128][40] (10240) + Ss fp16[32][136]
//   (8704). staging st f32[64][136] overlays.
// =====================================================================
__global__ void __launch_bounds__(256, 2) passB_kernel()
{
    extern __shared__ char shc[];
    const uint32_t base_u = smem_u32(shc);

    const int tid = threadIdx.x, lane = tid & 31, w = tid >> 5;
    const int ngg = w >> 1, hg = w & 1;
    const int r = lane >> 2, q = lane & 3;
    const int nt2 = blockIdx.x >> 1, ht = blockIdx.x & 1;
    const int ks = blockIdx.y, b = blockIdx.z;

    const __half* Pb  = g_Ph + ((size_t)b*256 + nt2*128)*M_PER_B;
    const __half* Sbh = g_Sh + (size_t)b*M_PER_B*256;

    float acc[64];
    #pragma unroll
    for (int i = 0; i < 64; i++) acc[i] = 0.f;
    float tsum = 0.f;

    auto copy_chunk = [&](int ch, int stage) {
        int mb = ks*1024 + ch*32;
        uint32_t pd = base_u + stage*18944;
        #pragma unroll
        for (int i = 0; i < 2; i++) {
            int idx = i*256 + tid;
            int row = idx >> 2, c = idx & 3;
            cp16(pd + (uint32_t)row*80 + c*16, Pb + (size_t)row*M_PER_B + mb + c*8);
        }
        uint32_t sd = pd + 10240;
        #pragma unroll
        for (int i = 0; i < 2; i++) {
            int idx = i*256 + tid;
            int row = idx >> 4, c = idx & 15;
            cp16(sd + (uint32_t)row*272 + c*16, Sbh + (size_t)(mb + row)*256 + ht*128 + c*8);
        }
    };

    const uint32_t aOff = (uint32_t)(ngg*32 + (lane & 15))*80 + (lane >> 4)*16;
    const uint32_t bOff = 10240u + (uint32_t)(lane & 15)*272 + hg*128 + (lane >> 4)*16;

    copy_chunk(0, 0);
    CP_COMMIT();

    for (int ch = 0; ch < 32; ch++) {
        if (ch == 0) { CP_WAIT0(); __syncthreads(); }
        if (ch + 1 < 32) { copy_chunk(ch + 1, (ch + 1) & 1); CP_COMMIT(); }

        uint32_t sb = base_u + (ch & 1)*18944;
        if (ht == 0 && tid < 128) {
            const __half2* pr = (const __half2*)(shc + (ch & 1)*18944 + tid*80);
            #pragma unroll
            for (int j = 0; j < 16; j++) {
                float2 f = __half22float2(pr[j]);
                tsum += f.x + f.y;
            }
        }
        #pragma unroll
        for (int step = 0; step < 2; step++) {
            uint32_t af0[4], af1[4];
            ldm_x4(af0, sb + aOff + step*32);
            ldm_x4(af1, sb + aOff + 1280 + step*32);
            #pragma unroll
            for (int p = 0; p < 4; p++) {
                uint32_t bf[4];
                ldm_x4t(bf, sb + bOff + step*4352 + p*32);
                mma16(acc + (p*2)*4,        af0, bf[0], bf[1]);
                mma16(acc + 32 + (p*2)*4,   af1, bf[0], bf[1]);
                mma16(acc + (p*2+1)*4,      af0, bf[2], bf[3]);
                mma16(acc + 32 + (p*2+1)*4, af1, bf[2], bf[3]);
            }
        }
        if (ch + 1 < 32) { CP_WAIT0(); }
        __syncthreads();
    }

    // ---- stage + coalesced partial writes (2 rounds of 64 n rows) ----
    float* st = (float*)shc;   // [64][136]
    float* Wb = g_W + ((((size_t)b*KS_B + ks)*2 + nt2)*128)*256 + ht*128;
    for (int half = 0; half < 2; half++) {
        __syncthreads();
        if ((ngg >> 1) == half) {
            #pragma unroll
            for (int mt = 0; mt < 2; mt++)
                #pragma unroll
                for (int p = 0; p < 8; p++) {
                    int row0 = (ngg & 1)*32 + mt*16 + r;
                    int h0 = hg*64 + p*8 + q*2;
                    *(float2*)&st[row0*136 + h0] =
                        make_float2(acc[mt*32 + p*4 + 0], acc[mt*32 + p*4 + 1]);
                    *(float2*)&st[(row0 + 8)*136 + h0] =
                        make_float2(acc[mt*32 + p*4 + 2], acc[mt*32 + p*4 + 3]);
                }
        }
        __syncthreads();
        #pragma unroll
        for (int i = 0; i < 8; i++) {
            int idx = i*256 + tid;
            int rr = idx >> 5, c = (idx & 31) << 2;
            *(float4*)(Wb + (size_t)(half*64 + rr)*256 + c) = *(const float4*)&st[rr*136 + c];
        }
    }
    if (ht == 0 && tid < 128)
        g_Wt[(((size_t)b*KS_B + ks)*2 + nt2)*128 + tid] = tsum;
}

// =====================================================================
// Kernel 4: reduce split-K; context = G@Wv + t*bv ; out = context@Wo + bo ;
//           y = LN(out + hidden)
// =====================================================================
__global__ void __launch_bounds__(256) final_kernel(
    const float* __restrict__ hidden,
    const float* __restrict__ Wv, const float* __restrict__ bv,
    const float* __restrict__ Wo, const float* __restrict__ bo,
    const float* __restrict__ gamma, const float* __restrict__ beta,
    float* __restrict__ out)
{
    int n = blockIdx.x, b = blockIdx.y, t = threadIdx.x;
    __shared__ float grow[256];
    __shared__ float crow[256];
    __shared__ float red[KS_B];
    __shared__ float wsum[8];

    int nt = n >> 7, nl = n & 127;
    float g = 0.f;
    #pragma unroll 8
    for (int ks = 0; ks < KS_B; ks++)
        g += g_W[((((size_t)b*KS_B + ks)*2 + nt)*128 + nl)*256 + t];
    grow[t] = g;
    if (t < KS_B)
        red[t] = g_Wt[(((size_t)b*KS_B + t)*2 + nt)*128 + nl];
    __syncthreads();

    float tsum = 0.f;
    #pragma unroll
    for (int i = 0; i < KS_B; i++) tsum += red[i];

    float c = tsum * bv[t];
    #pragma unroll 8
    for (int h = 0; h < 256; h++) c += grow[h] * Wv[h*256 + t];
    crow[t] = c;
    __syncthreads();

    float o = bo[t];
    #pragma unroll 8
    for (int d = 0; d < 256; d++) o += crow[d] * Wo[d*256 + t];
    float x = o + hidden[(b*256 + n)*256 + t];

    int lane = t & 31, w = t >> 5;
    float s = x;
    #pragma unroll
    for (int of = 16; of > 0; of >>= 1) s += __shfl_xor_sync(0xffffffffu, s, of);
    if (lane == 0) wsum[w] = s;
    __syncthreads();
    float tot = 0.f;
    #pragma unroll
    for (int i = 0; i < 8; i++) tot += wsum[i];
    float mean = tot * (1.f/256.f);
    float dx = x - mean;
    __syncthreads();

    float s2 = dx * dx;
    #pragma unroll
    for (int of = 16; of > 0; of >>= 1) s2 += __shfl_xor_sync(0xffffffffu, s2, of);
    if (lane == 0) wsum[w] = s2;
    __syncthreads();
    float tot2 = 0.f;
    #pragma unroll
    for (int i = 0; i < 8; i++) tot2 += wsum[i];
    float var = tot2 * (1.f/256.f);

    out[(b*256 + n)*256 + t] = gamma[t] * dx * rsqrtf(var + 1e-5f) + beta[t];
}

// =====================================================================
extern "C" void kernel_launch(void* const* d_in, const int* in_sizes, int n_in,
                              void* d_out, int out_size)
{
    const float* hidden = (const float*)d_in[0];
    const float* S      = (const float*)d_in[1];
    const float* am     = (const float*)d_in[2];
    const float* Wq     = (const float*)d_in[3];
    const float* bq     = (const float*)d_in[4];
    const float* Wk     = (const float*)d_in[5];
    const float* bk     = (const float*)d_in[6];
    const float* Wv     = (const float*)d_in[7];
    const float* bv     = (const float*)d_in[8];
    const float* Wo     = (const float*)d_in[9];
    const float* bo     = (const float*)d_in[10];
    const float* gamma  = (const float*)d_in[11];
    const float* beta   = (const float*)d_in[12];
    float* out          = (float*)d_out;

    const int smemA = 53248;   // 2x25600 stages + csm(1K) + rsum(512) ; sth 36864 overlays
    const int smemB = 38912;   // 2x18944 stages ; st f32 64x136 (34816) overlays
    cudaFuncSetAttribute(passA_kernel, cudaFuncAttributeMaxDynamicSharedMemorySize, smemA);
    cudaFuncSetAttribute(passB_kernel, cudaFuncAttributeMaxDynamicSharedMemorySize, smemB);

    prep_kernel<<<dim3(256, 4), 256>>>(hidden, Wq, bq, Wk, bk);
    passA_kernel<<<dim3(M_PER_B/64, 4), 256, smemA>>>(S, am);
    passB_kernel<<<dim3(4, KS_B, 4), 256, smemB>>>();
    final_kernel<<<dim3(256, 4), 256>>>(hidden, Wv, bv, Wo, bo, gamma, beta, out);
}